// round 5
// baseline (speedup 1.0000x reference)
#include <cuda_runtime.h>
#include <math.h>
#include <stdint.h>

// ---------------- problem constants ----------------
#define BB    4
#define HH    32
#define KVH   8
#define DD    128
#define HID   4096
#define SC    8191          // cache length
#define SS    8192          // total sequence
#define WW    512           // blocks (S/BLK)
#define BLK   16
#define HIST  64
#define NSEL  64            // TOPK/BLK
#define MAXBL 80            // 64 topk + 8 forced, padded

#define KSPL  8             // k-splits for GEMVs
#define NCOL  (HID + 1024 + 1024)   // 6144 qkv columns

#define NSTRIP 8            // h-strips for conv
#define HSTR   8            // rows per strip

typedef unsigned long long ull;

// packed fp32x2 FMA (Blackwell): two exact IEEE fp32 FMAs per instruction
#define FMA_F32X2(d, a, b, c) \
    asm("fma.rn.f32x2 %0, %1, %2, %3;" : "=l"(d) : "l"(a), "l"(b), "l"(c))
#define PACK_DUP(d, x) \
    asm("mov.b64 %0, {%1, %2};" : "=l"(d) : "f"(x), "f"(x))
#define UNPACK2(lo, hi, q) \
    asm("mov.b64 {%0, %1}, %2;" : "=f"(lo), "=f"(hi) : "l"(q))

// ---------------- device scratch ----------------
__device__ float g_part [KSPL * BB * NCOL];          // qkv gemv partials
__device__ float g_q    [BB * HH * DD];              // roped q
__device__ float g_kn   [BB * KVH * DD];             // roped new k
__device__ float g_vn   [BB * KVH * DD];             // new v
__device__ float g_cpart[NSTRIP * BB * HH * WW];     // conv strip partials
__device__ int   g_blist[BB * HH * MAXBL];           // selected block lists
__device__ int   g_bcnt [BB * HH];
__device__ float g_ctx  [BB * HID];                  // attention output
__device__ float g_opart[KSPL * BB * HID];           // Wo gemv partials

// ================= QKV GEMV: partials =================
__global__ void k_qkv(const float* __restrict__ hid,
                      const float* __restrict__ Wq,
                      const float* __restrict__ Wk,
                      const float* __restrict__ Wv) {
    __shared__ float hs[BB][512];
    const int ks = blockIdx.y;
    const int k0 = ks * 512;
    for (int i = threadIdx.x; i < BB * 512; i += 256) {
        int b = i >> 9, kk = i & 511;
        hs[b][kk] = hid[b * HID + k0 + kk];
    }
    __syncthreads();

    const int c = blockIdx.x * 256 + threadIdx.x;   // 0..6143
    const float* Wm; int ld, cc;
    if (c < HID)              { Wm = Wq; ld = HID;  cc = c; }
    else if (c < HID + 1024)  { Wm = Wk; ld = 1024; cc = c - HID; }
    else                      { Wm = Wv; ld = 1024; cc = c - HID - 1024; }

    float a0 = 0.f, a1 = 0.f, a2 = 0.f, a3 = 0.f;
    const float* p = Wm + (size_t)k0 * ld + cc;
#pragma unroll 8
    for (int kk = 0; kk < 512; ++kk) {
        float w = p[(size_t)kk * ld];
        a0 = fmaf(hs[0][kk], w, a0);
        a1 = fmaf(hs[1][kk], w, a1);
        a2 = fmaf(hs[2][kk], w, a2);
        a3 = fmaf(hs[3][kk], w, a3);
    }
    g_part[((ks * BB + 0) * NCOL) + c] = a0;
    g_part[((ks * BB + 1) * NCOL) + c] = a1;
    g_part[((ks * BB + 2) * NCOL) + c] = a2;
    g_part[((ks * BB + 3) * NCOL) + c] = a3;
}

// ================= fused reduce + RoPE =================
__global__ void k_rope(const float* __restrict__ cosb, const float* __restrict__ sinb) {
    int i = blockIdx.x * 256 + threadIdx.x;      // < BB*NCOL
    if (i >= BB * NCOL) return;
    int b = i / NCOL, c = i - b * NCOL;
    float v = 0.f;
#pragma unroll
    for (int ks = 0; ks < KSPL; ++ks) v += g_part[(ks * BB + b) * NCOL + c];

    if (c < HID + 1024) {   // q or k : apply rope
        int d = c & (DD - 1);
        int pair = (d < DD / 2) ? c + DD / 2 : c - DD / 2;
        float pv = 0.f;
#pragma unroll
        for (int ks = 0; ks < KSPL; ++ks) pv += g_part[(ks * BB + b) * NCOL + pair];
        float cs = cosb[b * DD + d];
        float sn = sinb[b * DD + d];
        float rot = (d < DD / 2) ? -pv : pv;
        float out = v * cs + rot * sn;
        if (c < HID) g_q[b * HID + c] = out;
        else         g_kn[b * (KVH * DD) + (c - HID)] = out;
    } else {
        g_vn[b * (KVH * DD) + (c - HID - 1024)] = v;
    }
}

// ================= fused CNN, h-striped, f32x2 conv2 (R2-proven layout) ======
// static smem ~48.2KB, 3 CTAs/SM
__global__ void __launch_bounds__(256, 3)
k_conv(const float* __restrict__ hist,
       const float* __restrict__ c1w, const float* __restrict__ c1b,
       const float* __restrict__ c2w, const float* __restrict__ c2b,
       const float* __restrict__ c3w, const float* __restrict__ c3b) {
    __shared__ float y1s[16 * 10 * 36];   // conv1 out: [c1][sh 0..9][wi 0..35]
    __shared__ float sx [12 * 36];        // input strip with halo
    __shared__ float w2s[144 * 32];       // conv2 weights, k-major, c2 contiguous
    __shared__ float w1s[144];
    __shared__ float b1s[16];
    __shared__ float b2s[32];
    __shared__ float c3s[32];
    __shared__ float red[32 * 32];

    const int n   = blockIdx.z;            // image 0..127
    const int h0  = blockIdx.y * HSTR;     // strip base row
    const int w0  = blockIdx.x * 32;       // w tile base
    const int tid = threadIdx.x;

    // ---- load weights ----
    for (int i = tid; i < 144; i += 256) w1s[i] = c1w[i];
    if (tid < 16) b1s[tid] = c1b[tid];
    if (tid < 32) { b2s[tid] = c2b[tid]; c3s[tid] = c3w[tid]; }
    for (int i = tid; i < 32 * 144; i += 256) {
        int c2 = i & 31, kk = i >> 5;
        int c1 = kk / 9, r = kk - c1 * 9;
        w2s[kk * 32 + c2] = c2w[(c2 * 16 + c1) * 9 + r];
    }
    // ---- load x strip with halo, zero padded ----
    const float* xim = hist + (size_t)n * HIST * WW;
    for (int i = tid; i < 12 * 36; i += 256) {
        int sh = i / 36, sw = i - sh * 36;
        int h = h0 - 2 + sh, w = w0 - 2 + sw;
        float v = 0.f;
        if ((unsigned)h < 64u && (unsigned)w < 512u) v = xim[h * WW + w];
        sx[i] = v;
    }
    __syncthreads();

    // ---- conv1: rows sh 0..9 (hh = h0-1+sh), wi 0..33 ----
    for (int o = tid; o < 16 * 10 * 34; o += 256) {
        int c1 = o / 340;
        int r  = o - c1 * 340;
        int sh = r / 34;
        int wi = r - sh * 34;
        int hh = h0 - 1 + sh;
        int w  = w0 - 1 + wi;
        float v = 0.f;
        if ((unsigned)hh < 64u && (unsigned)w < 512u) {
            const float* wp = w1s + c1 * 9;
            float s = b1s[c1];
#pragma unroll
            for (int dh = 0; dh < 3; ++dh) {
                const float* xr = sx + (sh + dh) * 36 + wi;
                s = fmaf(wp[dh * 3 + 0], xr[0], s);
                s = fmaf(wp[dh * 3 + 1], xr[1], s);
                s = fmaf(wp[dh * 3 + 2], xr[2], s);
            }
            v = fmaxf(s, 0.f);
        }
        y1s[(c1 * 10 + sh) * 36 + wi] = v;
    }
    __syncthreads();

    // ---- conv2 with packed f32x2 (pairs over c2) ----
    const int wg  = tid & 7;            // 4 w each
    const int c2g = (tid >> 3) & 7;     // 4 c2 each
    const int hg  = tid >> 6;           // h within strip: hg, hg+4
    const int c2  = c2g * 4;

    float acc[4][4];
#pragma unroll
    for (int a = 0; a < 4; ++a)
#pragma unroll
        for (int i = 0; i < 4; ++i) acc[a][i] = 0.f;

    const ull bb0 = *(const ull*)(b2s + c2);       // (c2, c2+1)
    const ull bb1 = *(const ull*)(b2s + c2 + 2);   // (c2+2, c2+3)

#pragma unroll
    for (int t = 0; t < 2; ++t) {
        const int ho = hg + t * 4;      // output row within strip (0..7)
        ull y2p0[4], y2p1[4];
#pragma unroll
        for (int i = 0; i < 4; ++i) { y2p0[i] = bb0; y2p1[i] = bb1; }

        for (int c1 = 0; c1 < 16; ++c1) {
            const float* ybase = y1s + c1 * 360 + wg * 4;
            const float* wbase = w2s + c1 * 9 * 32 + c2;
#pragma unroll
            for (int dh = 0; dh < 3; ++dh) {
                const float* yr = ybase + (ho + dh) * 36;
                float4 ra = *(const float4*)(yr);
                float2 rb = *(const float2*)(yr + 4);
                ull rd[6];
                PACK_DUP(rd[0], ra.x); PACK_DUP(rd[1], ra.y);
                PACK_DUP(rd[2], ra.z); PACK_DUP(rd[3], ra.w);
                PACK_DUP(rd[4], rb.x); PACK_DUP(rd[5], rb.y);
#pragma unroll
                for (int dw = 0; dw < 3; ++dw) {
                    ulonglong2 wq = *(const ulonglong2*)(wbase + (dh * 3 + dw) * 32);
#pragma unroll
                    for (int i = 0; i < 4; ++i) {
                        FMA_F32X2(y2p0[i], wq.x, rd[i + dw], y2p0[i]);
                        FMA_F32X2(y2p1[i], wq.y, rd[i + dw], y2p1[i]);
                    }
                }
            }
        }
        // relu + accumulate over h
#pragma unroll
        for (int i = 0; i < 4; ++i) {
            float f0, f1, f2, f3;
            UNPACK2(f0, f1, y2p0[i]);
            UNPACK2(f2, f3, y2p1[i]);
            acc[0][i] += fmaxf(f0, 0.f);
            acc[1][i] += fmaxf(f1, 0.f);
            acc[2][i] += fmaxf(f2, 0.f);
            acc[3][i] += fmaxf(f3, 0.f);
        }
    }

    // ---- c3 dot, fixed-order reduction ----
    const int gid = hg * 8 + c2g;       // 0..31
#pragma unroll
    for (int i = 0; i < 4; ++i) {
        float s = acc[0][i] * c3s[c2] + acc[1][i] * c3s[c2 + 1] +
                  acc[2][i] * c3s[c2 + 2] + acc[3][i] * c3s[c2 + 3];
        red[gid * 32 + wg * 4 + i] = s;
    }
    __syncthreads();
    if (tid < 32) {
        float s = 0.f;
        for (int g = 0; g < 32; ++g) s += red[g * 32 + tid];
        g_cpart[((blockIdx.y * 128 + n) * WW) + w0 + tid] = s;
    }
}

// ===== top-k (64 of 512) with fused strip-reduce + forced sink/local blocks ====
__global__ void k_topk(const float* __restrict__ c3b) {
    const int bh = blockIdx.x;                    // 0..127
    __shared__ float v[WW];
    __shared__ unsigned char sel[WW];
    __shared__ float wv[8];
    __shared__ int   wix[8];
    const int tid = threadIdx.x;
    const int lane = tid & 31, wid = tid >> 5;
    const float bias = c3b[0];

    for (int i = tid; i < WW; i += 256) {
        float s = 0.f;
#pragma unroll
        for (int st = 0; st < NSTRIP; ++st) s += g_cpart[(st * 128 + bh) * WW + i];
        v[i] = s * (1.f / 64.f) + bias;
        sel[i] = 0;
    }
    __syncthreads();

    for (int it = 0; it < NSEL; ++it) {
        float bv = v[tid]; int bi = tid;
        float b2 = v[tid + 256];
        if (b2 > bv) { bv = b2; bi = tid + 256; }
#pragma unroll
        for (int o = 16; o > 0; o >>= 1) {
            float ov = __shfl_xor_sync(0xffffffffu, bv, o);
            int   oi = __shfl_xor_sync(0xffffffffu, bi, o);
            if (ov > bv || (ov == bv && oi < bi)) { bv = ov; bi = oi; }
        }
        if (lane == 0) { wv[wid] = bv; wix[wid] = bi; }
        __syncthreads();
        if (tid == 0) {
            float m = wv[0]; int mi = wix[0];
#pragma unroll
            for (int g = 1; g < 8; ++g)
                if (wv[g] > m || (wv[g] == m && wix[g] < mi)) { m = wv[g]; mi = wix[g]; }
            sel[mi] = 1; v[mi] = -3.0e38f;
        }
        __syncthreads();
    }
    if (tid == 0) {
        for (int i = 0; i < 4; ++i) { sel[i] = 1; sel[WW - 4 + i] = 1; }
        int cnt = 0;
        for (int w = 0; w < WW; ++w)
            if (sel[w]) g_blist[bh * MAXBL + (cnt++)] = w;
        g_bcnt[bh] = cnt;
    }
}

// ================= sparse attention (one CTA per (b,h)) =================
__global__ void k_attn(const float* __restrict__ kc, const float* __restrict__ vc) {
    const int bh = blockIdx.x;
    const int b = bh >> 5, h = bh & 31, kvh = h >> 2;
    const int tid = threadIdx.x;                  // 256
    __shared__ float qs[DD];
    __shared__ float sc[MAXBL * BLK];
    __shared__ float redf[256];
    __shared__ float vacc[8][DD];

    const int cnt  = g_bcnt[bh];
    const int ntok = cnt * BLK;
    if (tid < DD) qs[tid] = g_q[(b * HH + h) * DD + tid];
    __syncthreads();

    const int wid = tid >> 5, lane = tid & 31;
    const float iscale = 0.08838834764831845f;    // 1/sqrt(128)
    const float4 q4 = *(const float4*)(qs + lane * 4);
    const size_t kvbase = (size_t)(b * KVH + kvh) * SC;

    for (int t = wid; t < ntok; t += 8) {
        int blk = g_blist[bh * MAXBL + (t >> 4)];
        int s = blk * BLK + (t & 15);
        const float* kr = (s == SS - 1)
            ? (g_kn + (b * KVH + kvh) * DD)
            : (kc + (kvbase + s) * DD);
        float4 k4 = ((const float4*)kr)[lane];
        float sum = fmaf(q4.x, k4.x, fmaf(q4.y, k4.y, fmaf(q4.z, k4.z, q4.w * k4.w)));
#pragma unroll
        for (int o = 16; o > 0; o >>= 1) sum += __shfl_xor_sync(0xffffffffu, sum, o);
        if (lane == 0) sc[t] = sum * iscale;
    }
    __syncthreads();

    float m = -3.0e38f;
    for (int t = tid; t < ntok; t += 256) m = fmaxf(m, sc[t]);
    redf[tid] = m; __syncthreads();
    for (int st = 128; st > 0; st >>= 1) {
        if (tid < st) redf[tid] = fmaxf(redf[tid], redf[tid + st]);
        __syncthreads();
    }
    m = redf[0];
    __syncthreads();

    float lp = 0.f;
    for (int t = tid; t < ntok; t += 256) { float p = expf(sc[t] - m); sc[t] = p; lp += p; }
    redf[tid] = lp; __syncthreads();
    for (int st = 128; st > 0; st >>= 1) {
        if (tid < st) redf[tid] += redf[tid + st];
        __syncthreads();
    }
    const float linv = 1.f / redf[0];
    __syncthreads();

    // V pass: all 8 warps accumulate partials, fixed-order combine
    float4 a4 = make_float4(0.f, 0.f, 0.f, 0.f);
    for (int t = wid; t < ntok; t += 8) {
        int blk = g_blist[bh * MAXBL + (t >> 4)];
        int s = blk * BLK + (t & 15);
        const float* vr = (s == SS - 1)
            ? (g_vn + (b * KVH + kvh) * DD)
            : (vc + (kvbase + s) * DD);
        float4 v4 = ((const float4*)vr)[lane];
        float p = sc[t];
        a4.x = fmaf(p, v4.x, a4.x);
        a4.y = fmaf(p, v4.y, a4.y);
        a4.z = fmaf(p, v4.z, a4.z);
        a4.w = fmaf(p, v4.w, a4.w);
    }
    *(float4*)(&vacc[wid][lane * 4]) = a4;
    __syncthreads();

    if (tid < DD) {
        float s = 0.f;
#pragma unroll
        for (int g = 0; g < 8; ++g) s += vacc[g][tid];
        g_ctx[b * HID + h * DD + tid] = s * linv;
    }
}

// ================= Wo GEMV =================
__global__ void k_out(const float* __restrict__ Wo) {
    __shared__ float cs[BB][512];
    const int ks = blockIdx.y;
    const int k0 = ks * 512;
    for (int i = threadIdx.x; i < BB * 512; i += 256) {
        int b = i >> 9, kk = i & 511;
        cs[b][kk] = g_ctx[b * HID + k0 + kk];
    }
    __syncthreads();
    const int c = blockIdx.x * 256 + threadIdx.x;
    float a0 = 0.f, a1 = 0.f, a2 = 0.f, a3 = 0.f;
    const float* p = Wo + (size_t)k0 * HID + c;
#pragma unroll 8
    for (int kk = 0; kk < 512; ++kk) {
        float w = p[(size_t)kk * HID];
        a0 = fmaf(cs[0][kk], w, a0);
        a1 = fmaf(cs[1][kk], w, a1);
        a2 = fmaf(cs[2][kk], w, a2);
        a3 = fmaf(cs[3][kk], w, a3);
    }
    g_opart[(ks * BB + 0) * HID + c] = a0;
    g_opart[(ks * BB + 1) * HID + c] = a1;
    g_opart[(ks * BB + 2) * HID + c] = a2;
    g_opart[(ks * BB + 3) * HID + c] = a3;
}

__global__ void k_red_out(float* __restrict__ out) {
    int i = blockIdx.x * 256 + threadIdx.x;
    if (i >= BB * HID) return;
    int b = i / HID, c = i - b * HID;
    float s = 0.f;
#pragma unroll
    for (int ks = 0; ks < KSPL; ++ks) s += g_opart[(ks * BB + b) * HID + c];
    out[i] = s;
}

// ================= host launcher =================
extern "C" void kernel_launch(void* const* d_in, const int* in_sizes, int n_in,
                              void* d_out, int out_size) {
    const float* hid  = (const float*)d_in[0];
    const float* kc   = (const float*)d_in[1];
    const float* vc   = (const float*)d_in[2];
    const float* hist = (const float*)d_in[3];
    const float* cosb = (const float*)d_in[4];
    const float* sinb = (const float*)d_in[5];
    const float* Wq   = (const float*)d_in[6];
    const float* Wk   = (const float*)d_in[7];
    const float* Wv   = (const float*)d_in[8];
    const float* Wo   = (const float*)d_in[9];
    const float* c1w  = (const float*)d_in[10];
    const float* c1b  = (const float*)d_in[11];
    const float* c2w  = (const float*)d_in[12];
    const float* c2b  = (const float*)d_in[13];
    const float* c3w  = (const float*)d_in[14];
    const float* c3b  = (const float*)d_in[15];
    float* out = (float*)d_out;

    k_qkv    <<<dim3(NCOL / 256, KSPL), 256>>>(hid, Wq, Wk, Wv);
    k_rope   <<<(BB * NCOL + 255) / 256, 256>>>(cosb, sinb);
    k_conv   <<<dim3(WW / 32, NSTRIP, BB * HH), 256>>>(hist, c1w, c1b, c2w, c2b, c3w, c3b);
    k_topk   <<<BB * HH, 256>>>(c3b);
    k_attn   <<<BB * HH, 256>>>(kc, vc);
    k_out    <<<dim3(HID / 256, KSPL), 256>>>(Wo);
    k_red_out<<<(BB * HID + 255) / 256, 256>>>(out);
}

// round 8
// speedup vs baseline: 1.2793x; 1.2793x over previous
#include <cuda_runtime.h>
#include <cuda_fp16.h>
#include <math.h>
#include <stdint.h>

#define BB    4
#define HH    32
#define KVH   8
#define DD    128
#define HID   4096
#define SC    8191
#define SS    8192
#define WW    512
#define BLK   16
#define NSEL  64
#define MAXBL 80
#define KSPL  8
#define NCOL  (HID + 1024 + 1024)

// ---------------- device scratch ----------------
__device__ float g_part [KSPL * BB * NCOL];
__device__ float g_q    [BB * HH * DD];
__device__ float g_kn   [BB * KVH * DD];
__device__ float g_vn   [BB * KVH * DD];
__device__ float g_tsp  [BB * HH * WW];
__device__ int   g_blist[BB * HH * MAXBL];
__device__ int   g_bcnt [BB * HH];
__device__ float g_ctx  [BB * HID];
__device__ float g_opart[KSPL * BB * HID];
__device__ unsigned short g_Bt[2 * 9 * 32 * 16];   // fp16 weight limbs [(lb*9+t)*32+c2]*16+c1

// ================= warp-mma helpers (plain sm_103 features only) =============
__device__ __forceinline__ uint32_t smem_u32(const void* p) {
    uint32_t a;
    asm("{ .reg .u64 t; cvta.to.shared.u64 t, %1; cvt.u32.u64 %0, t; }" : "=r"(a) : "l"(p));
    return a;
}
#define LDSM_X4(r0, r1, r2, r3, addr) \
    asm volatile("ldmatrix.sync.aligned.m8n8.x4.shared.b16 {%0,%1,%2,%3}, [%4];" \
        : "=r"(r0), "=r"(r1), "=r"(r2), "=r"(r3) : "r"(addr))
#define LDSM_X2(r0, r1, addr) \
    asm volatile("ldmatrix.sync.aligned.m8n8.x2.shared.b16 {%0,%1}, [%2];" \
        : "=r"(r0), "=r"(r1) : "r"(addr))
#define MMA16816(d, a0, a1, a2, a3, b0, b1) \
    asm volatile("mma.sync.aligned.m16n8k16.row.col.f32.f16.f16.f32 " \
        "{%0,%1,%2,%3}, {%4,%5,%6,%7}, {%8,%9}, {%0,%1,%2,%3};" \
        : "+f"((d)[0]), "+f"((d)[1]), "+f"((d)[2]), "+f"((d)[3]) \
        : "r"(a0), "r"(a1), "r"(a2), "r"(a3), "r"(b0), "r"(b1))

// ================= QKV GEMV =================
__global__ void k_qkv(const float* __restrict__ hid, const float* __restrict__ Wq,
                      const float* __restrict__ Wk, const float* __restrict__ Wv) {
    __shared__ float hs[BB][512];
    const int ks = blockIdx.y, k0 = ks * 512;
    for (int i = threadIdx.x; i < BB * 512; i += 256) {
        int b = i >> 9, kk = i & 511;
        hs[b][kk] = hid[b * HID + k0 + kk];
    }
    __syncthreads();
    const int c = blockIdx.x * 256 + threadIdx.x;
    const float* Wm; int ld, cc;
    if (c < HID)              { Wm = Wq; ld = HID;  cc = c; }
    else if (c < HID + 1024)  { Wm = Wk; ld = 1024; cc = c - HID; }
    else                      { Wm = Wv; ld = 1024; cc = c - HID - 1024; }
    float a0 = 0.f, a1 = 0.f, a2 = 0.f, a3 = 0.f;
    const float* p = Wm + (size_t)k0 * ld + cc;
#pragma unroll 8
    for (int kk = 0; kk < 512; ++kk) {
        float w = p[(size_t)kk * ld];
        a0 = fmaf(hs[0][kk], w, a0);
        a1 = fmaf(hs[1][kk], w, a1);
        a2 = fmaf(hs[2][kk], w, a2);
        a3 = fmaf(hs[3][kk], w, a3);
    }
    g_part[((ks * BB + 0) * NCOL) + c] = a0;
    g_part[((ks * BB + 1) * NCOL) + c] = a1;
    g_part[((ks * BB + 2) * NCOL) + c] = a2;
    g_part[((ks * BB + 3) * NCOL) + c] = a3;
}

// ================= reduce + RoPE =================
__global__ void k_rope(const float* __restrict__ cosb, const float* __restrict__ sinb) {
    int i = blockIdx.x * 256 + threadIdx.x;
    if (i >= BB * NCOL) return;
    int b = i / NCOL, c = i - b * NCOL;
    float v = 0.f;
#pragma unroll
    for (int ks = 0; ks < KSPL; ++ks) v += g_part[(ks * BB + b) * NCOL + c];
    if (c < HID + 1024) {
        int d = c & (DD - 1);
        int pair = (d < DD / 2) ? c + DD / 2 : c - DD / 2;
        float pv = 0.f;
#pragma unroll
        for (int ks = 0; ks < KSPL; ++ks) pv += g_part[(ks * BB + b) * NCOL + pair];
        float cs = cosb[b * DD + d], sn = sinb[b * DD + d];
        float rot = (d < DD / 2) ? -pv : pv;
        float out = v * cs + rot * sn;
        if (c < HID) g_q[b * HID + c] = out;
        else         g_kn[b * (KVH * DD) + (c - HID)] = out;
    } else {
        g_vn[b * (KVH * DD) + (c - HID - 1024)] = v;
    }
}

// ====== conv2 weight prep: 2 exact fp16 limbs (low limb pre-scaled by 2048) ===
__global__ void k_prep(const float* __restrict__ c2w) {
    int idx = blockIdx.x * 256 + threadIdx.x;
    if (idx >= 4608) return;
    int c2 = idx / 144, rem = idx - c2 * 144;
    int c1 = rem / 9, t = rem - c1 * 9;      // t = dh*3+dw
    float a = c2w[idx];
    __half h = __float2half(a);
    float r = (a - __half2float(h)) * 2048.f;
    __half l = __float2half(r);
    g_Bt[((0 * 9 + t) * 32 + c2) * 16 + c1] = __half_as_ushort(h);
    g_Bt[((1 * 9 + t) * 32 + c2) * 16 + c1] = __half_as_ushort(l);
}

// ================= mma.sync conv2: CTA = 128 w-pixels of one image ============
#define A_PLANE_H 3120
#define A_SLOT_B  12480           // bytes per slot (2 limb planes)
#define CONV2_SMEM (77568 + 2480 + 16)

__device__ __forceinline__ void build_row(
    int hb, int W0, int tid, const float* __restrict__ xim,
    float* xs, const float* w1s, const float* b1s, __half* As)
{
    const bool act = (hb < 64);
    if (act) {
        for (int i = tid; i < 3 * 132; i += 256) {
            int r = i / 132, c = i - r * 132;
            int hh = hb - 1 + r, w = W0 - 2 + c;
            float v = 0.f;
            if ((unsigned)hh < 64u && (unsigned)w < 512u) v = xim[hh * WW + w];
            xs[i] = v;
        }
    }
    __syncthreads();
    if (act) {
        __half* dst = As + (hb & 3) * (2 * A_PLANE_H);
        for (int o = tid; o < 130 * 16; o += 256) {
            int wi = o >> 4, c1 = o & 15;
            float v = 0.f;
            if ((unsigned)(W0 - 1 + wi) < 512u) {
                const float* wp = w1s + c1 * 9;
                float s = b1s[c1];
#pragma unroll
                for (int dh = 0; dh < 3; ++dh) {
                    s = fmaf(wp[dh * 3 + 0], xs[dh * 132 + wi], s);
                    s = fmaf(wp[dh * 3 + 1], xs[dh * 132 + wi + 1], s);
                    s = fmaf(wp[dh * 3 + 2], xs[dh * 132 + wi + 2], s);
                }
                v = fmaxf(s, 0.f);
            }
            __half hv = __float2half(v);
            float res = (v - __half2float(hv)) * 2048.f;
            __half lv = __float2half(res);
            dst[wi * 24 + c1] = hv;
            dst[A_PLANE_H + wi * 24 + c1] = lv;
        }
    }
    __syncthreads();   // protect xs against next call's load phase
}

__global__ void __launch_bounds__(256, 1)
k_conv2(const float* __restrict__ hist,
        const float* __restrict__ c1w, const float* __restrict__ c1b,
        const float* __restrict__ c2b, const float* __restrict__ c3w,
        const float* __restrict__ c3b) {
    extern __shared__ __align__(16) unsigned char smraw[];
    __half* As = (__half*)smraw;               // 24960 halves
    __half* Bs = As + 24960;                   // 13824 halves
    float*  xs = (float*)(Bs + 13824);         // 396
    float* w1s = xs + 396;                     // 144
    float* b1s = w1s + 144;                    // 16
    float* b2s = b1s + 16;                     // 32
    float* c3s = b2s + 32;                     // 32
    __shared__ float redp[8][32];              // per-warp c2-half partials

    const int n   = blockIdx.y;
    const int W0  = blockIdx.x * 128;
    const int tid = threadIdx.x;
    const int lane = tid & 31, wid = tid >> 5;
    const int wm = wid >> 1, wn = wid & 1;     // m-block (32 w), n-half (16 c2)

    for (int i = tid; i < 144; i += 256) w1s[i] = c1w[i];
    if (tid < 16) b1s[tid] = c1b[tid];
    if (tid < 32) { b2s[tid] = c2b[tid]; c3s[tid] = c3w[tid]; }
    // B limbs -> padded smem tiles [tile 72][n8][k24]
    for (int i = tid; i < 2 * 9 * 32 * 16; i += 256) {
        int k = i & 15, c2 = (i >> 4) & 31, t = i >> 9;   // t = lb*9 + dhdw
        Bs[(t * 4 + (c2 >> 3)) * 192 + (c2 & 7) * 24 + k] =
            __ushort_as_half(g_Bt[i]);
    }
    __syncthreads();

    const float* xim = hist + (size_t)n * 64 * WW;
    build_row(0, W0, tid, xim, xs, w1s, b1s, As);
    build_row(1, W0, tid, xim, xs, w1s, b1s, As);

    // ---- load B fragments once (held in registers across the h loop) ----
    const uint32_t Bb = smem_u32(Bs);
    const uint32_t blo = (uint32_t)((lane & 7) * 48 + (((lane >> 3) & 1) << 4));
    uint32_t bH0[18], bH1[18], bL0[18], bL1[18];
#pragma unroll
    for (int t = 0; t < 9; ++t) {
#pragma unroll
        for (int ntl = 0; ntl < 2; ++ntl) {
            int j = t * 2 + ntl;
            LDSM_X2(bH0[j], bH1[j], Bb + (uint32_t)(((0 + t) * 4 + wn * 2 + ntl) * 384) + blo);
            LDSM_X2(bL0[j], bL1[j], Bb + (uint32_t)(((9 + t) * 4 + wn * 2 + ntl) * 384) + blo);
        }
    }

    // epilogue constants (per-thread fixed c2 columns)
    float b2r[2][2], c3r[2][2];
#pragma unroll
    for (int ntl = 0; ntl < 2; ++ntl)
#pragma unroll
        for (int lo = 0; lo < 2; ++lo) {
            int c2 = wn * 16 + ntl * 8 + 2 * (lane & 3) + lo;
            b2r[ntl][lo] = b2s[c2];
            c3r[ntl][lo] = c3s[c2];
        }

    const uint32_t Ab = smem_u32(As);
    const uint32_t arow = (uint32_t)((lane & 15) * 48 + ((lane >> 4) << 4));
    const float INV2048 = 4.8828125e-4f;
    float racc[4] = {0.f, 0.f, 0.f, 0.f};

    for (int h = 0; h < 64; ++h) {
        float accM[2][2][4], accC[2][2][4];
#pragma unroll
        for (int mt = 0; mt < 2; ++mt)
#pragma unroll
            for (int ntl = 0; ntl < 2; ++ntl)
#pragma unroll
                for (int i = 0; i < 4; ++i) { accM[mt][ntl][i] = 0.f; accC[mt][ntl][i] = 0.f; }

#pragma unroll
        for (int dh = 0; dh < 3; ++dh) {
            int hr = h - 1 + dh;
            if ((unsigned)hr < 64u) {
                uint32_t pH = Ab + (uint32_t)(hr & 3) * A_SLOT_B;
#pragma unroll
                for (int dw = 0; dw < 3; ++dw) {
#pragma unroll
                    for (int mt = 0; mt < 2; ++mt) {
                        uint32_t ra = pH + (uint32_t)((wm * 32 + mt * 16 + dw) * 48) + arow;
                        uint32_t h0, h1, h2, h3, l0, l1, l2, l3;
                        LDSM_X4(h0, h1, h2, h3, ra);
                        LDSM_X4(l0, l1, l2, l3, ra + 6240);
                        int j = (dh * 3 + dw) * 2;
#pragma unroll
                        for (int ntl = 0; ntl < 2; ++ntl) {
                            MMA16816(accM[mt][ntl], h0, h1, h2, h3, bH0[j + ntl], bH1[j + ntl]);
                            MMA16816(accC[mt][ntl], l0, l1, l2, l3, bH0[j + ntl], bH1[j + ntl]);
                            MMA16816(accC[mt][ntl], h0, h1, h2, h3, bL0[j + ntl], bL1[j + ntl]);
                        }
                    }
                }
            }
        }
        // epilogue: bias + relu + c3 dot over this warp's 16 c2, accumulate over h
#pragma unroll
        for (int mt = 0; mt < 2; ++mt)
#pragma unroll
            for (int ntl = 0; ntl < 2; ++ntl)
#pragma unroll
                for (int i = 0; i < 4; ++i) {
                    float d = accM[mt][ntl][i] + accC[mt][ntl][i] * INV2048 + b2r[ntl][i & 1];
                    racc[mt * 2 + (i >> 1)] += fmaxf(d, 0.f) * c3r[ntl][i & 1];
                }
        build_row(h + 2, W0, tid, xim, xs, w1s, b1s, As);
    }

    // quad reduce (fixed order): sum cols within the warp's n8 tiles
#pragma unroll
    for (int j = 0; j < 4; ++j) {
        racc[j] += __shfl_xor_sync(0xffffffffu, racc[j], 1);
        racc[j] += __shfl_xor_sync(0xffffffffu, racc[j], 2);
    }
    if ((lane & 3) == 0) {
        int q = lane >> 2;
#pragma unroll
        for (int j = 0; j < 4; ++j) redp[wid][j * 8 + q] = racc[j];
    }
    __syncthreads();

    // combine the two c2-halves (wn=0 + wn=1) deterministically and write
    if (tid < 128) {
        int wm2 = tid >> 5, idx = tid & 31;
        int j = idx >> 3, q = idx & 7;
        float s = redp[wm2 * 2 + 0][idx] + redp[wm2 * 2 + 1][idx];
        int w = W0 + wm2 * 32 + (j >> 1) * 16 + ((j & 1) << 3) + q;
        g_tsp[n * WW + w] = s * (1.f / 64.f) + c3b[0];
    }
}

// ================= top-k + forced sink/local =================
__global__ void k_topk() {
    const int bh = blockIdx.x;
    __shared__ float v[WW];
    __shared__ unsigned char sel[WW];
    __shared__ float wv[8];
    __shared__ int   wix[8];
    const int tid = threadIdx.x, lane = tid & 31, wid = tid >> 5;

    for (int i = tid; i < WW; i += 256) { v[i] = g_tsp[bh * WW + i]; sel[i] = 0; }
    __syncthreads();
    for (int it = 0; it < NSEL; ++it) {
        float bv = v[tid]; int bi = tid;
        float b2 = v[tid + 256];
        if (b2 > bv) { bv = b2; bi = tid + 256; }
#pragma unroll
        for (int o = 16; o > 0; o >>= 1) {
            float ov = __shfl_xor_sync(0xffffffffu, bv, o);
            int   oi = __shfl_xor_sync(0xffffffffu, bi, o);
            if (ov > bv || (ov == bv && oi < bi)) { bv = ov; bi = oi; }
        }
        if (lane == 0) { wv[wid] = bv; wix[wid] = bi; }
        __syncthreads();
        if (tid == 0) {
            float m = wv[0]; int mi = wix[0];
#pragma unroll
            for (int g = 1; g < 8; ++g)
                if (wv[g] > m || (wv[g] == m && wix[g] < mi)) { m = wv[g]; mi = wix[g]; }
            sel[mi] = 1; v[mi] = -3.0e38f;
        }
        __syncthreads();
    }
    if (tid == 0) {
        for (int i = 0; i < 4; ++i) { sel[i] = 1; sel[WW - 4 + i] = 1; }
        int cnt = 0;
        for (int w = 0; w < WW; ++w)
            if (sel[w]) g_blist[bh * MAXBL + (cnt++)] = w;
        g_bcnt[bh] = cnt;
    }
}

// ================= sparse attention =================
__global__ void k_attn(const float* __restrict__ kc, const float* __restrict__ vc) {
    const int bh = blockIdx.x;
    const int b = bh >> 5, h = bh & 31, kvh = h >> 2;
    const int tid = threadIdx.x;
    __shared__ float qs[DD];
    __shared__ float sc[MAXBL * BLK];
    __shared__ float redf[256];
    __shared__ float vacc[8][DD];

    const int cnt = g_bcnt[bh];
    const int ntok = cnt * BLK;
    if (tid < DD) qs[tid] = g_q[(b * HH + h) * DD + tid];
    __syncthreads();

    const int wid = tid >> 5, lane = tid & 31;
    const float iscale = 0.08838834764831845f;
    const float4 q4 = *(const float4*)(qs + lane * 4);
    const size_t kvbase = (size_t)(b * KVH + kvh) * SC;

    for (int t = wid; t < ntok; t += 8) {
        int blk = g_blist[bh * MAXBL + (t >> 4)];
        int s = blk * BLK + (t & 15);
        const float* kr = (s == SS - 1) ? (g_kn + (b * KVH + kvh) * DD)
                                        : (kc + (kvbase + s) * DD);
        float4 k4 = ((const float4*)kr)[lane];
        float sum = fmaf(q4.x, k4.x, fmaf(q4.y, k4.y, fmaf(q4.z, k4.z, q4.w * k4.w)));
#pragma unroll
        for (int o = 16; o > 0; o >>= 1) sum += __shfl_xor_sync(0xffffffffu, sum, o);
        if (lane == 0) sc[t] = sum * iscale;
    }
    __syncthreads();

    float m = -3.0e38f;
    for (int t = tid; t < ntok; t += 256) m = fmaxf(m, sc[t]);
    redf[tid] = m; __syncthreads();
    for (int st = 128; st > 0; st >>= 1) {
        if (tid < st) redf[tid] = fmaxf(redf[tid], redf[tid + st]);
        __syncthreads();
    }
    m = redf[0];
    __syncthreads();

    float lp = 0.f;
    for (int t = tid; t < ntok; t += 256) { float p = expf(sc[t] - m); sc[t] = p; lp += p; }
    redf[tid] = lp; __syncthreads();
    for (int st = 128; st > 0; st >>= 1) {
        if (tid < st) redf[tid] += redf[tid + st];
        __syncthreads();
    }
    const float linv = 1.f / redf[0];
    __syncthreads();

    float4 a4 = make_float4(0.f, 0.f, 0.f, 0.f);
    for (int t = wid; t < ntok; t += 8) {
        int blk = g_blist[bh * MAXBL + (t >> 4)];
        int s = blk * BLK + (t & 15);
        const float* vr = (s == SS - 1) ? (g_vn + (b * KVH + kvh) * DD)
                                        : (vc + (kvbase + s) * DD);
        float4 v4 = ((const float4*)vr)[lane];
        float p = sc[t];
        a4.x = fmaf(p, v4.x, a4.x);
        a4.y = fmaf(p, v4.y, a4.y);
        a4.z = fmaf(p, v4.z, a4.z);
        a4.w = fmaf(p, v4.w, a4.w);
    }
    *(float4*)(&vacc[wid][lane * 4]) = a4;
    __syncthreads();

    if (tid < DD) {
        float s = 0.f;
#pragma unroll
        for (int g = 0; g < 8; ++g) s += vacc[g][tid];
        g_ctx[b * HID + h * DD + tid] = s * linv;
    }
}

// ================= Wo GEMV =================
__global__ void k_out(const float* __restrict__ Wo) {
    __shared__ float cs[BB][512];
    const int ks = blockIdx.y, k0 = ks * 512;
    for (int i = threadIdx.x; i < BB * 512; i += 256) {
        int b = i >> 9, kk = i & 511;
        cs[b][kk] = g_ctx[b * HID + k0 + kk];
    }
    __syncthreads();
    const int c = blockIdx.x * 256 + threadIdx.x;
    float a0 = 0.f, a1 = 0.f, a2 = 0.f, a3 = 0.f;
    const float* p = Wo + (size_t)k0 * HID + c;
#pragma unroll 8
    for (int kk = 0; kk < 512; ++kk) {
        float w = p[(size_t)kk * HID];
        a0 = fmaf(cs[0][kk], w, a0);
        a1 = fmaf(cs[1][kk], w, a1);
        a2 = fmaf(cs[2][kk], w, a2);
        a3 = fmaf(cs[3][kk], w, a3);
    }
    g_opart[(ks * BB + 0) * HID + c] = a0;
    g_opart[(ks * BB + 1) * HID + c] = a1;
    g_opart[(ks * BB + 2) * HID + c] = a2;
    g_opart[(ks * BB + 3) * HID + c] = a3;
}

__global__ void k_red_out(float* __restrict__ out) {
    int i = blockIdx.x * 256 + threadIdx.x;
    if (i >= BB * HID) return;
    int b = i / HID, c = i - b * HID;
    float s = 0.f;
#pragma unroll
    for (int ks = 0; ks < KSPL; ++ks) s += g_opart[(ks * BB + b) * HID + c];
    out[i] = s;
}

// ================= host launcher =================
extern "C" void kernel_launch(void* const* d_in, const int* in_sizes, int n_in,
                              void* d_out, int out_size) {
    const float* hid  = (const float*)d_in[0];
    const float* kc   = (const float*)d_in[1];
    const float* vc   = (const float*)d_in[2];
    const float* hist = (const float*)d_in[3];
    const float* cosb = (const float*)d_in[4];
    const float* sinb = (const float*)d_in[5];
    const float* Wq   = (const float*)d_in[6];
    const float* Wk   = (const float*)d_in[7];
    const float* Wv   = (const float*)d_in[8];
    const float* Wo   = (const float*)d_in[9];
    const float* c1w  = (const float*)d_in[10];
    const float* c1b  = (const float*)d_in[11];
    const float* c2w  = (const float*)d_in[12];
    const float* c2b  = (const float*)d_in[13];
    const float* c3w  = (const float*)d_in[14];
    const float* c3b  = (const float*)d_in[15];
    float* out = (float*)d_out;

    cudaFuncSetAttribute(k_conv2, cudaFuncAttributeMaxDynamicSharedMemorySize, CONV2_SMEM);

    k_qkv    <<<dim3(NCOL / 256, KSPL), 256>>>(hid, Wq, Wk, Wv);
    k_rope   <<<(BB * NCOL + 255) / 256, 256>>>(cosb, sinb);
    k_prep   <<<18, 256>>>(c2w);
    k_conv2  <<<dim3(4, BB * HH), 256, CONV2_SMEM>>>(hist, c1w, c1b, c2b, c3w, c3b);
    k_topk   <<<BB * HH, 256>>>();
    k_attn   <<<BB * HH, 256>>>(kc, vc);
    k_out    <<<dim3(HID / 256, KSPL), 256>>>(Wo);
    k_red_out<<<(BB * HID + 255) / 256, 256>>>(out);
}

// round 9
// speedup vs baseline: 1.7387x; 1.3591x over previous
#include <cuda_runtime.h>
#include <cuda_fp16.h>
#include <math.h>
#include <stdint.h>

#define BB    4
#define HH    32
#define KVH   8
#define DD    128
#define HID   4096
#define SC    8191
#define SS    8192
#define WW    512
#define BLK   16
#define NSEL  64
#define MAXBL 80
#define KSPL  8
#define NCOL  (HID + 1024 + 1024)

// ---------------- device scratch ----------------
__device__ float g_part [KSPL * BB * NCOL];
__device__ float g_q    [BB * HH * DD];
__device__ float g_kn   [BB * KVH * DD];
__device__ float g_vn   [BB * KVH * DD];
__device__ float g_tsp  [BB * HH * WW];
__device__ int   g_blist[BB * HH * MAXBL];
__device__ int   g_bcnt [BB * HH];
__device__ float g_ctx  [BB * HID];
__device__ float g_opart[KSPL * BB * HID];
__device__ unsigned short g_Bt[2 * 9 * 32 * 16];   // fp16 weight limbs [(lb*9+t)*32+c2]*16+c1

// ================= warp-mma helpers (plain sm_103 features only) =============
__device__ __forceinline__ uint32_t smem_u32(const void* p) {
    uint32_t a;
    asm("{ .reg .u64 t; cvta.to.shared.u64 t, %1; cvt.u32.u64 %0, t; }" : "=r"(a) : "l"(p));
    return a;
}
#define LDSM_X4(r0, r1, r2, r3, addr) \
    asm volatile("ldmatrix.sync.aligned.m8n8.x4.shared.b16 {%0,%1,%2,%3}, [%4];" \
        : "=r"(r0), "=r"(r1), "=r"(r2), "=r"(r3) : "r"(addr))
#define LDSM_X2(r0, r1, addr) \
    asm volatile("ldmatrix.sync.aligned.m8n8.x2.shared.b16 {%0,%1}, [%2];" \
        : "=r"(r0), "=r"(r1) : "r"(addr))
#define MMA16816(d, a0, a1, a2, a3, b0, b1) \
    asm volatile("mma.sync.aligned.m16n8k16.row.col.f32.f16.f16.f32 " \
        "{%0,%1,%2,%3}, {%4,%5,%6,%7}, {%8,%9}, {%0,%1,%2,%3};" \
        : "+f"((d)[0]), "+f"((d)[1]), "+f"((d)[2]), "+f"((d)[3]) \
        : "r"(a0), "r"(a1), "r"(a2), "r"(a3), "r"(b0), "r"(b1))

// ================= QKV GEMV =================
__global__ void k_qkv(const float* __restrict__ hid, const float* __restrict__ Wq,
                      const float* __restrict__ Wk, const float* __restrict__ Wv) {
    __shared__ float hs[BB][512];
    const int ks = blockIdx.y, k0 = ks * 512;
    for (int i = threadIdx.x; i < BB * 512; i += 256) {
        int b = i >> 9, kk = i & 511;
        hs[b][kk] = hid[b * HID + k0 + kk];
    }
    __syncthreads();
    const int c = blockIdx.x * 256 + threadIdx.x;
    const float* Wm; int ld, cc;
    if (c < HID)              { Wm = Wq; ld = HID;  cc = c; }
    else if (c < HID + 1024)  { Wm = Wk; ld = 1024; cc = c - HID; }
    else                      { Wm = Wv; ld = 1024; cc = c - HID - 1024; }
    float a0 = 0.f, a1 = 0.f, a2 = 0.f, a3 = 0.f;
    const float* p = Wm + (size_t)k0 * ld + cc;
#pragma unroll 8
    for (int kk = 0; kk < 512; ++kk) {
        float w = p[(size_t)kk * ld];
        a0 = fmaf(hs[0][kk], w, a0);
        a1 = fmaf(hs[1][kk], w, a1);
        a2 = fmaf(hs[2][kk], w, a2);
        a3 = fmaf(hs[3][kk], w, a3);
    }
    g_part[((ks * BB + 0) * NCOL) + c] = a0;
    g_part[((ks * BB + 1) * NCOL) + c] = a1;
    g_part[((ks * BB + 2) * NCOL) + c] = a2;
    g_part[((ks * BB + 3) * NCOL) + c] = a3;
}

// ================= reduce + RoPE =================
__global__ void k_rope(const float* __restrict__ cosb, const float* __restrict__ sinb) {
    int i = blockIdx.x * 256 + threadIdx.x;
    if (i >= BB * NCOL) return;
    int b = i / NCOL, c = i - b * NCOL;
    float v = 0.f;
#pragma unroll
    for (int ks = 0; ks < KSPL; ++ks) v += g_part[(ks * BB + b) * NCOL + c];
    if (c < HID + 1024) {
        int d = c & (DD - 1);
        int pair = (d < DD / 2) ? c + DD / 2 : c - DD / 2;
        float pv = 0.f;
#pragma unroll
        for (int ks = 0; ks < KSPL; ++ks) pv += g_part[(ks * BB + b) * NCOL + pair];
        float cs = cosb[b * DD + d], sn = sinb[b * DD + d];
        float rot = (d < DD / 2) ? -pv : pv;
        float out = v * cs + rot * sn;
        if (c < HID) g_q[b * HID + c] = out;
        else         g_kn[b * (KVH * DD) + (c - HID)] = out;
    } else {
        g_vn[b * (KVH * DD) + (c - HID - 1024)] = v;
    }
}

// ====== conv2 weight prep: 2 exact fp16 limbs (low limb pre-scaled by 2048) ===
__global__ void k_prep(const float* __restrict__ c2w) {
    int idx = blockIdx.x * 256 + threadIdx.x;
    if (idx >= 4608) return;
    int c2 = idx / 144, rem = idx - c2 * 144;
    int c1 = rem / 9, t = rem - c1 * 9;      // t = dh*3+dw
    float a = c2w[idx];
    __half h = __float2half(a);
    float r = (a - __half2float(h)) * 2048.f;
    __half l = __float2half(r);
    g_Bt[((0 * 9 + t) * 32 + c2) * 16 + c1] = __half_as_ushort(h);
    g_Bt[((1 * 9 + t) * 32 + c2) * 16 + c1] = __half_as_ushort(l);
}

// ================= mma.sync conv2: CTA = 128 w-pixels of one image ============
#define A_PLANE_H 3120
#define A_SLOT_B  12480           // bytes per slot (2 limb planes)
#define CONV2_SMEM (77568 + 2480 + 16)

__device__ __forceinline__ void build_row(
    int hb, int W0, int tid, const float* __restrict__ xim,
    float* xs, const float* w1s, const float* b1s, __half* As)
{
    const bool act = (hb < 64);
    if (act) {
        for (int i = tid; i < 3 * 132; i += 256) {
            int r = i / 132, c = i - r * 132;
            int hh = hb - 1 + r, w = W0 - 2 + c;
            float v = 0.f;
            if ((unsigned)hh < 64u && (unsigned)w < 512u) v = xim[hh * WW + w];
            xs[i] = v;
        }
    }
    __syncthreads();
    if (act) {
        __half* dst = As + (hb & 3) * (2 * A_PLANE_H);
        for (int o = tid; o < 130 * 16; o += 256) {
            int wi = o >> 4, c1 = o & 15;
            float v = 0.f;
            if ((unsigned)(W0 - 1 + wi) < 512u) {
                const float* wp = w1s + c1 * 9;
                float s = b1s[c1];
#pragma unroll
                for (int dh = 0; dh < 3; ++dh) {
                    s = fmaf(wp[dh * 3 + 0], xs[dh * 132 + wi], s);
                    s = fmaf(wp[dh * 3 + 1], xs[dh * 132 + wi + 1], s);
                    s = fmaf(wp[dh * 3 + 2], xs[dh * 132 + wi + 2], s);
                }
                v = fmaxf(s, 0.f);
            }
            __half hv = __float2half(v);
            float res = (v - __half2float(hv)) * 2048.f;
            __half lv = __float2half(res);
            dst[wi * 24 + c1] = hv;
            dst[A_PLANE_H + wi * 24 + c1] = lv;
        }
    }
    __syncthreads();   // protect xs against next call's load phase
}

__global__ void __launch_bounds__(256, 2)
k_conv2(const float* __restrict__ hist,
        const float* __restrict__ c1w, const float* __restrict__ c1b,
        const float* __restrict__ c2b, const float* __restrict__ c3w,
        const float* __restrict__ c3b) {
    extern __shared__ __align__(16) unsigned char smraw[];
    __half* As = (__half*)smraw;               // 24960 halves
    __half* Bs = As + 24960;                   // 13824 halves
    float*  xs = (float*)(Bs + 13824);         // 396
    float* w1s = xs + 396;                     // 144
    float* b1s = w1s + 144;                    // 16
    float* b2s = b1s + 16;                     // 32
    float* c3s = b2s + 32;                     // 32
    __shared__ float redp[8][32];              // per-warp c2-half partials

    const int n   = blockIdx.y;
    const int W0  = blockIdx.x * 128;
    const int tid = threadIdx.x;
    const int lane = tid & 31, wid = tid >> 5;
    const int wm = wid >> 1, wn = wid & 1;     // m-block (32 w), n-half (16 c2)

    for (int i = tid; i < 144; i += 256) w1s[i] = c1w[i];
    if (tid < 16) b1s[tid] = c1b[tid];
    if (tid < 32) { b2s[tid] = c2b[tid]; c3s[tid] = c3w[tid]; }
    // B limbs -> padded smem tiles [tile 72][n8][k24]
    for (int i = tid; i < 2 * 9 * 32 * 16; i += 256) {
        int k = i & 15, c2 = (i >> 4) & 31, t = i >> 9;   // t = lb*9 + dhdw
        Bs[(t * 4 + (c2 >> 3)) * 192 + (c2 & 7) * 24 + k] =
            __ushort_as_half(g_Bt[i]);
    }
    __syncthreads();

    const float* xim = hist + (size_t)n * 64 * WW;
    build_row(0, W0, tid, xim, xs, w1s, b1s, As);
    build_row(1, W0, tid, xim, xs, w1s, b1s, As);

    // ---- high-limb B fragments held in registers; low limbs reloaded per use --
    const uint32_t Bb = smem_u32(Bs);
    const uint32_t blo = (uint32_t)((lane & 7) * 48 + (((lane >> 3) & 1) << 4));
    uint32_t bH0[18], bH1[18];
#pragma unroll
    for (int t = 0; t < 9; ++t) {
#pragma unroll
        for (int ntl = 0; ntl < 2; ++ntl) {
            int j = t * 2 + ntl;
            LDSM_X2(bH0[j], bH1[j], Bb + (uint32_t)((t * 4 + wn * 2 + ntl) * 384) + blo);
        }
    }

    // epilogue constants (per-thread fixed c2 columns)
    float b2r[2][2], c3r[2][2];
#pragma unroll
    for (int ntl = 0; ntl < 2; ++ntl)
#pragma unroll
        for (int lo = 0; lo < 2; ++lo) {
            int c2 = wn * 16 + ntl * 8 + 2 * (lane & 3) + lo;
            b2r[ntl][lo] = b2s[c2];
            c3r[ntl][lo] = c3s[c2];
        }

    const uint32_t Ab = smem_u32(As);
    const uint32_t arow = (uint32_t)((lane & 15) * 48 + ((lane >> 4) << 4));
    const float INV2048 = 4.8828125e-4f;
    float racc[4] = {0.f, 0.f, 0.f, 0.f};

    for (int h = 0; h < 64; ++h) {
        float accM[2][2][4], accC[2][2][4];
#pragma unroll
        for (int mt = 0; mt < 2; ++mt)
#pragma unroll
            for (int ntl = 0; ntl < 2; ++ntl)
#pragma unroll
                for (int i = 0; i < 4; ++i) { accM[mt][ntl][i] = 0.f; accC[mt][ntl][i] = 0.f; }

#pragma unroll
        for (int dh = 0; dh < 3; ++dh) {
            int hr = h - 1 + dh;
            if ((unsigned)hr < 64u) {
                uint32_t pH = Ab + (uint32_t)(hr & 3) * A_SLOT_B;
#pragma unroll
                for (int dw = 0; dw < 3; ++dw) {
                    const int t9 = dh * 3 + dw;
                    // reload low-limb B fragments (frees 36 long-lived regs)
                    uint32_t bl0[2], bl1[2];
#pragma unroll
                    for (int ntl = 0; ntl < 2; ++ntl)
                        LDSM_X2(bl0[ntl], bl1[ntl],
                                Bb + (uint32_t)(((9 + t9) * 4 + wn * 2 + ntl) * 384) + blo);
#pragma unroll
                    for (int mt = 0; mt < 2; ++mt) {
                        uint32_t ra = pH + (uint32_t)((wm * 32 + mt * 16 + dw) * 48) + arow;
                        uint32_t h0, h1, h2, h3, l0, l1, l2, l3;
                        LDSM_X4(h0, h1, h2, h3, ra);
                        LDSM_X4(l0, l1, l2, l3, ra + 6240);
                        int j = t9 * 2;
#pragma unroll
                        for (int ntl = 0; ntl < 2; ++ntl) {
                            MMA16816(accM[mt][ntl], h0, h1, h2, h3, bH0[j + ntl], bH1[j + ntl]);
                            MMA16816(accC[mt][ntl], l0, l1, l2, l3, bH0[j + ntl], bH1[j + ntl]);
                            MMA16816(accC[mt][ntl], h0, h1, h2, h3, bl0[ntl], bl1[ntl]);
                        }
                    }
                }
            }
        }
        // epilogue: bias + relu + c3 dot over this warp's 16 c2, accumulate over h
#pragma unroll
        for (int mt = 0; mt < 2; ++mt)
#pragma unroll
            for (int ntl = 0; ntl < 2; ++ntl)
#pragma unroll
                for (int i = 0; i < 4; ++i) {
                    float d = accM[mt][ntl][i] + accC[mt][ntl][i] * INV2048 + b2r[ntl][i & 1];
                    racc[mt * 2 + (i >> 1)] += fmaxf(d, 0.f) * c3r[ntl][i & 1];
                }
        build_row(h + 2, W0, tid, xim, xs, w1s, b1s, As);
    }

    // quad reduce (fixed order): sum cols within the warp's n8 tiles
#pragma unroll
    for (int j = 0; j < 4; ++j) {
        racc[j] += __shfl_xor_sync(0xffffffffu, racc[j], 1);
        racc[j] += __shfl_xor_sync(0xffffffffu, racc[j], 2);
    }
    if ((lane & 3) == 0) {
        int q = lane >> 2;
#pragma unroll
        for (int j = 0; j < 4; ++j) redp[wid][j * 8 + q] = racc[j];
    }
    __syncthreads();

    // combine the two c2-halves (wn=0 + wn=1) deterministically and write
    if (tid < 128) {
        int wm2 = tid >> 5, idx = tid & 31;
        int j = idx >> 3, q = idx & 7;
        float s = redp[wm2 * 2 + 0][idx] + redp[wm2 * 2 + 1][idx];
        int w = W0 + wm2 * 32 + (j >> 1) * 16 + ((j & 1) << 3) + q;
        g_tsp[n * WW + w] = s * (1.f / 64.f) + c3b[0];
    }
}

// ================= top-k + forced sink/local =================
__global__ void k_topk() {
    const int bh = blockIdx.x;
    __shared__ float v[WW];
    __shared__ unsigned char sel[WW];
    __shared__ float wv[8];
    __shared__ int   wix[8];
    const int tid = threadIdx.x, lane = tid & 31, wid = tid >> 5;

    for (int i = tid; i < WW; i += 256) { v[i] = g_tsp[bh * WW + i]; sel[i] = 0; }
    __syncthreads();
    for (int it = 0; it < NSEL; ++it) {
        float bv = v[tid]; int bi = tid;
        float b2 = v[tid + 256];
        if (b2 > bv) { bv = b2; bi = tid + 256; }
#pragma unroll
        for (int o = 16; o > 0; o >>= 1) {
            float ov = __shfl_xor_sync(0xffffffffu, bv, o);
            int   oi = __shfl_xor_sync(0xffffffffu, bi, o);
            if (ov > bv || (ov == bv && oi < bi)) { bv = ov; bi = oi; }
        }
        if (lane == 0) { wv[wid] = bv; wix[wid] = bi; }
        __syncthreads();
        if (tid == 0) {
            float m = wv[0]; int mi = wix[0];
#pragma unroll
            for (int g = 1; g < 8; ++g)
                if (wv[g] > m || (wv[g] == m && wix[g] < mi)) { m = wv[g]; mi = wix[g]; }
            sel[mi] = 1; v[mi] = -3.0e38f;
        }
        __syncthreads();
    }
    if (tid == 0) {
        for (int i = 0; i < 4; ++i) { sel[i] = 1; sel[WW - 4 + i] = 1; }
        int cnt = 0;
        for (int w = 0; w < WW; ++w)
            if (sel[w]) g_blist[bh * MAXBL + (cnt++)] = w;
        g_bcnt[bh] = cnt;
    }
}

// ================= sparse attention (512 threads / CTA) =================
__global__ void k_attn(const float* __restrict__ kc, const float* __restrict__ vc) {
    const int bh = blockIdx.x;
    const int b = bh >> 5, h = bh & 31, kvh = h >> 2;
    const int tid = threadIdx.x;                  // 512
    __shared__ float qs[DD];
    __shared__ float sc[MAXBL * BLK];
    __shared__ float redf[512];
    __shared__ float vacc[16][DD];

    const int cnt = g_bcnt[bh];
    const int ntok = cnt * BLK;
    if (tid < DD) qs[tid] = g_q[(b * HH + h) * DD + tid];
    __syncthreads();

    const int wid = tid >> 5, lane = tid & 31;    // 16 warps
    const float iscale = 0.08838834764831845f;
    const float4 q4 = *(const float4*)(qs + lane * 4);
    const size_t kvbase = (size_t)(b * KVH + kvh) * SC;

    for (int t = wid; t < ntok; t += 16) {
        int blk = g_blist[bh * MAXBL + (t >> 4)];
        int s = blk * BLK + (t & 15);
        const float* kr = (s == SS - 1) ? (g_kn + (b * KVH + kvh) * DD)
                                        : (kc + (kvbase + s) * DD);
        float4 k4 = ((const float4*)kr)[lane];
        float sum = fmaf(q4.x, k4.x, fmaf(q4.y, k4.y, fmaf(q4.z, k4.z, q4.w * k4.w)));
#pragma unroll
        for (int o = 16; o > 0; o >>= 1) sum += __shfl_xor_sync(0xffffffffu, sum, o);
        if (lane == 0) sc[t] = sum * iscale;
    }
    __syncthreads();

    float m = -3.0e38f;
    for (int t = tid; t < ntok; t += 512) m = fmaxf(m, sc[t]);
    redf[tid] = m; __syncthreads();
    for (int st = 256; st > 0; st >>= 1) {
        if (tid < st) redf[tid] = fmaxf(redf[tid], redf[tid + st]);
        __syncthreads();
    }
    m = redf[0];
    __syncthreads();

    float lp = 0.f;
    for (int t = tid; t < ntok; t += 512) { float p = expf(sc[t] - m); sc[t] = p; lp += p; }
    redf[tid] = lp; __syncthreads();
    for (int st = 256; st > 0; st >>= 1) {
        if (tid < st) redf[tid] += redf[tid + st];
        __syncthreads();
    }
    const float linv = 1.f / redf[0];
    __syncthreads();

    float4 a4 = make_float4(0.f, 0.f, 0.f, 0.f);
    for (int t = wid; t < ntok; t += 16) {
        int blk = g_blist[bh * MAXBL + (t >> 4)];
        int s = blk * BLK + (t & 15);
        const float* vr = (s == SS - 1) ? (g_vn + (b * KVH + kvh) * DD)
                                        : (vc + (kvbase + s) * DD);
        float4 v4 = ((const float4*)vr)[lane];
        float p = sc[t];
        a4.x = fmaf(p, v4.x, a4.x);
        a4.y = fmaf(p, v4.y, a4.y);
        a4.z = fmaf(p, v4.z, a4.z);
        a4.w = fmaf(p, v4.w, a4.w);
    }
    *(float4*)(&vacc[wid][lane * 4]) = a4;
    __syncthreads();

    if (tid < DD) {
        float s = 0.f;
#pragma unroll
        for (int g = 0; g < 16; ++g) s += vacc[g][tid];
        g_ctx[b * HID + h * DD + tid] = s * linv;
    }
}

// ================= Wo GEMV =================
__global__ void k_out(const float* __restrict__ Wo) {
    __shared__ float cs[BB][512];
    const int ks = blockIdx.y, k0 = ks * 512;
    for (int i = threadIdx.x; i < BB * 512; i += 256) {
        int b = i >> 9, kk = i & 511;
        cs[b][kk] = g_ctx[b * HID + k0 + kk];
    }
    __syncthreads();
    const int c = blockIdx.x * 256 + threadIdx.x;
    float a0 = 0.f, a1 = 0.f, a2 = 0.f, a3 = 0.f;
    const float* p = Wo + (size_t)k0 * HID + c;
#pragma unroll 8
    for (int kk = 0; kk < 512; ++kk) {
        float w = p[(size_t)kk * HID];
        a0 = fmaf(cs[0][kk], w, a0);
        a1 = fmaf(cs[1][kk], w, a1);
        a2 = fmaf(cs[2][kk], w, a2);
        a3 = fmaf(cs[3][kk], w, a3);
    }
    g_opart[(ks * BB + 0) * HID + c] = a0;
    g_opart[(ks * BB + 1) * HID + c] = a1;
    g_opart[(ks * BB + 2) * HID + c] = a2;
    g_opart[(ks * BB + 3) * HID + c] = a3;
}

__global__ void k_red_out(float* __restrict__ out) {
    int i = blockIdx.x * 256 + threadIdx.x;
    if (i >= BB * HID) return;
    int b = i / HID, c = i - b * HID;
    float s = 0.f;
#pragma unroll
    for (int ks = 0; ks < KSPL; ++ks) s += g_opart[(ks * BB + b) * HID + c];
    out[i] = s;
}

// ================= host launcher =================
extern "C" void kernel_launch(void* const* d_in, const int* in_sizes, int n_in,
                              void* d_out, int out_size) {
    const float* hid  = (const float*)d_in[0];
    const float* kc   = (const float*)d_in[1];
    const float* vc   = (const float*)d_in[2];
    const float* hist = (const float*)d_in[3];
    const float* cosb = (const float*)d_in[4];
    const float* sinb = (const float*)d_in[5];
    const float* Wq   = (const float*)d_in[6];
    const float* Wk   = (const float*)d_in[7];
    const float* Wv   = (const float*)d_in[8];
    const float* Wo   = (const float*)d_in[9];
    const float* c1w  = (const float*)d_in[10];
    const float* c1b  = (const float*)d_in[11];
    const float* c2w  = (const float*)d_in[12];
    const float* c2b  = (const float*)d_in[13];
    const float* c3w  = (const float*)d_in[14];
    const float* c3b  = (const float*)d_in[15];
    float* out = (float*)d_out;

    cudaFuncSetAttribute(k_conv2, cudaFuncAttributeMaxDynamicSharedMemorySize, CONV2_SMEM);

    k_qkv    <<<dim3(NCOL / 256, KSPL), 256>>>(hid, Wq, Wk, Wv);
    k_rope   <<<(BB * NCOL + 255) / 256, 256>>>(cosb, sinb);
    k_prep   <<<18, 256>>>(c2w);
    k_conv2  <<<dim3(4, BB * HH), 256, CONV2_SMEM>>>(hist, c1w, c1b, c2b, c3w, c3b);
    k_topk   <<<BB * HH, 256>>>();
    k_attn   <<<BB * HH, 512>>>(kc, vc);
    k_out    <<<dim3(HID / 256, KSPL), 256>>>(Wo);
    k_red_out<<<(BB * HID + 255) / 256, 256>>>(out);
}

// round 11
// speedup vs baseline: 1.9513x; 1.1223x over previous
#include <cuda_runtime.h>
#include <cuda_fp16.h>
#include <math.h>
#include <stdint.h>

#define BB    4
#define HH    32
#define KVH   8
#define DD    128
#define HID   4096
#define SC    8191
#define SS    8192
#define WW    512
#define BLK   16
#define NSEL  64
#define MAXBL 80
#define KSPL  8
#define NCOL  (HID + 1024 + 1024)

// ---------------- device scratch ----------------
__device__ float g_part [KSPL * BB * NCOL];
__device__ float g_q    [BB * HH * DD];
__device__ float g_kn   [BB * KVH * DD];
__device__ float g_vn   [BB * KVH * DD];
__device__ float g_tsp  [BB * HH * WW];
__device__ int   g_blist[BB * HH * MAXBL];
__device__ int   g_bcnt [BB * HH];
__device__ float g_ctx  [BB * HID];
__device__ float g_opart[KSPL * BB * HID];
__device__ unsigned short g_Bt[2 * 9 * 32 * 16];   // fp16 limbs of 64*w  [(lb*9+t)*32+c2]*16+c1

// ================= warp-mma helpers =================
__device__ __forceinline__ uint32_t smem_u32(const void* p) {
    uint32_t a;
    asm("{ .reg .u64 t; cvta.to.shared.u64 t, %1; cvt.u32.u64 %0, t; }" : "=r"(a) : "l"(p));
    return a;
}
#define LDSM_X4(r0, r1, r2, r3, addr) \
    asm volatile("ldmatrix.sync.aligned.m8n8.x4.shared.b16 {%0,%1,%2,%3}, [%4];" \
        : "=r"(r0), "=r"(r1), "=r"(r2), "=r"(r3) : "r"(addr))
#define LDSM_X2(r0, r1, addr) \
    asm volatile("ldmatrix.sync.aligned.m8n8.x2.shared.b16 {%0,%1}, [%2];" \
        : "=r"(r0), "=r"(r1) : "r"(addr))
#define MMA16816(d, a0, a1, a2, a3, b0, b1) \
    asm volatile("mma.sync.aligned.m16n8k16.row.col.f32.f16.f16.f32 " \
        "{%0,%1,%2,%3}, {%4,%5,%6,%7}, {%8,%9}, {%0,%1,%2,%3};" \
        : "+f"((d)[0]), "+f"((d)[1]), "+f"((d)[2]), "+f"((d)[3]) \
        : "r"(a0), "r"(a1), "r"(a2), "r"(a3), "r"(b0), "r"(b1))

#define A_PLANE_HALF 3120        // halves per limb plane (130 rows x 24)
#define A_SLOT_B     12480       // bytes per slot (2 limb planes)

// ================= QKV GEMV =================
__global__ void k_qkv(const float* __restrict__ hid, const float* __restrict__ Wq,
                      const float* __restrict__ Wk, const float* __restrict__ Wv) {
    __shared__ float hs[BB][512];
    const int ks = blockIdx.y, k0 = ks * 512;
    for (int i = threadIdx.x; i < BB * 512; i += 256) {
        int b = i >> 9, kk = i & 511;
        hs[b][kk] = hid[b * HID + k0 + kk];
    }
    __syncthreads();
    const int c = blockIdx.x * 256 + threadIdx.x;
    const float* Wm; int ld, cc;
    if (c < HID)              { Wm = Wq; ld = HID;  cc = c; }
    else if (c < HID + 1024)  { Wm = Wk; ld = 1024; cc = c - HID; }
    else                      { Wm = Wv; ld = 1024; cc = c - HID - 1024; }
    float a0 = 0.f, a1 = 0.f, a2 = 0.f, a3 = 0.f;
    const float* p = Wm + (size_t)k0 * ld + cc;
#pragma unroll 8
    for (int kk = 0; kk < 512; ++kk) {
        float w = p[(size_t)kk * ld];
        a0 = fmaf(hs[0][kk], w, a0);
        a1 = fmaf(hs[1][kk], w, a1);
        a2 = fmaf(hs[2][kk], w, a2);
        a3 = fmaf(hs[3][kk], w, a3);
    }
    g_part[((ks * BB + 0) * NCOL) + c] = a0;
    g_part[((ks * BB + 1) * NCOL) + c] = a1;
    g_part[((ks * BB + 2) * NCOL) + c] = a2;
    g_part[((ks * BB + 3) * NCOL) + c] = a3;
}

// ================= reduce + RoPE =================
__global__ void k_rope(const float* __restrict__ cosb, const float* __restrict__ sinb) {
    int i = blockIdx.x * 256 + threadIdx.x;
    if (i >= BB * NCOL) return;
    int b = i / NCOL, c = i - b * NCOL;
    float v = 0.f;
#pragma unroll
    for (int ks = 0; ks < KSPL; ++ks) v += g_part[(ks * BB + b) * NCOL + c];
    if (c < HID + 1024) {
        int d = c & (DD - 1);
        int pair = (d < DD / 2) ? c + DD / 2 : c - DD / 2;
        float pv = 0.f;
#pragma unroll
        for (int ks = 0; ks < KSPL; ++ks) pv += g_part[(ks * BB + b) * NCOL + pair];
        float cs = cosb[b * DD + d], sn = sinb[b * DD + d];
        float rot = (d < DD / 2) ? -pv : pv;
        float out = v * cs + rot * sn;
        if (c < HID) g_q[b * HID + c] = out;
        else         g_kn[b * (KVH * DD) + (c - HID)] = out;
    } else {
        g_vn[b * (KVH * DD) + (c - HID - 1024)] = v;
    }
}

// ====== conv2 weight prep: fp16 limbs of 64*w (all limbs normal-range) =========
__global__ void k_prep(const float* __restrict__ c2w) {
    int idx = blockIdx.x * 256 + threadIdx.x;
    if (idx >= 4608) return;
    int c2 = idx / 144, rem = idx - c2 * 144;
    int c1 = rem / 9, t = rem - c1 * 9;      // t = dh*3+dw
    float a = c2w[idx] * 64.f;
    __half h = __float2half(a);
    __half l = __float2half(a - __half2float(h));
    g_Bt[((0 * 9 + t) * 32 + c2) * 16 + c1] = __half_as_ushort(h);
    g_Bt[((1 * 9 + t) * 32 + c2) * 16 + c1] = __half_as_ushort(l);
}

// ================= mma.sync conv2: CTA = 128 w-pixels of one image ============
#define CONV2_SMEM 55296

__device__ __forceinline__ void build_row(
    int hb, int W0, int tid, const float* __restrict__ xim,
    float* xs, const float* w1s, const float* b1s, __half* As)
{
    const bool act = (hb < 64);
    if (act) {
        for (int i = tid; i < 3 * 132; i += 256) {
            int rr = i / 132, c = i - rr * 132;
            int hh = hb - 1 + rr, w = W0 - 2 + c;
            float v = 0.f;
            if ((unsigned)hh < 64u && (unsigned)w < 512u) v = xim[hh * WW + w];
            xs[i] = v;
        }
    }
    __syncthreads();
    if (act && tid < 130) {
        const int wi = tid;
        const bool valid = ((unsigned)(W0 - 1 + wi) < 512u);
        float x[9];
#pragma unroll
        for (int rr = 0; rr < 3; ++rr) {
            x[rr * 3 + 0] = xs[rr * 132 + wi];
            x[rr * 3 + 1] = xs[rr * 132 + wi + 1];
            x[rr * 3 + 2] = xs[rr * 132 + wi + 2];
        }
        __half* dst = As + (hb & 1) * 6240 + wi * 24;
        uint32_t oh[8], ol[8];
#pragma unroll
        for (int c1 = 0; c1 < 16; ++c1) {
            const float4 wa = *(const float4*)(w1s + c1 * 12);
            const float4 wb = *(const float4*)(w1s + c1 * 12 + 4);
            const float  w8 = w1s[c1 * 12 + 8];
            float s = b1s[c1];
            s = fmaf(wa.x, x[0], s); s = fmaf(wa.y, x[1], s); s = fmaf(wa.z, x[2], s);
            s = fmaf(wa.w, x[3], s); s = fmaf(wb.x, x[4], s); s = fmaf(wb.y, x[5], s);
            s = fmaf(wb.z, x[6], s); s = fmaf(wb.w, x[7], s); s = fmaf(w8,  x[8], s);
            float v = valid ? fmaxf(s, 0.f) : 0.f;
            __half hv = __float2half(v);
            __half lv = __float2half(v - __half2float(hv));
            uint32_t hb_ = (uint32_t)__half_as_ushort(hv);
            uint32_t lb_ = (uint32_t)__half_as_ushort(lv);
            if (c1 & 1) { oh[c1 >> 1] |= hb_ << 16; ol[c1 >> 1] |= lb_ << 16; }
            else        { oh[c1 >> 1] = hb_;        ol[c1 >> 1] = lb_; }
        }
        ((uint4*)dst)[0] = make_uint4(oh[0], oh[1], oh[2], oh[3]);
        ((uint4*)dst)[1] = make_uint4(oh[4], oh[5], oh[6], oh[7]);
        ((uint4*)(dst + A_PLANE_HALF))[0] = make_uint4(ol[0], ol[1], ol[2], ol[3]);
        ((uint4*)(dst + A_PLANE_HALF))[1] = make_uint4(ol[4], ol[5], ol[6], ol[7]);
    }
    __syncthreads();
}

__device__ __forceinline__ void epi_slot(float (&Ds)[2][2][4], float (&racc)[4],
                                         const float (&b2r)[2][2], const float (&c3r)[2][2]) {
#pragma unroll
    for (int mt = 0; mt < 2; ++mt)
#pragma unroll
        for (int ntl = 0; ntl < 2; ++ntl)
#pragma unroll
            for (int i = 0; i < 4; ++i) {
                float d = Ds[mt][ntl][i] * 0.015625f + b2r[ntl][i & 1];
                racc[mt * 2 + (i >> 1)] += fmaxf(d, 0.f) * c3r[ntl][i & 1];
                Ds[mt][ntl][i] = 0.f;
            }
}

template<int TN, int TC, int TP>
__device__ __forceinline__ void conv_step(int r,
    float (&D)[3][2][2][4], float (&racc)[4],
    uint32_t Ab, uint32_t Bb,
    const uint32_t (&bH0)[18], const uint32_t (&bH1)[18],
    int wm, int wn, uint32_t arow, uint32_t blo,
    const float (&b2r)[2][2], const float (&c3r)[2][2],
    int W0, int tid, const float* __restrict__ xim,
    float* xs, const float* w1s, const float* b1s, __half* As)
{
    const uint32_t pH = Ab + (uint32_t)((r & 1) * A_SLOT_B);
#pragma unroll
    for (int dw = 0; dw < 3; ++dw) {
        uint32_t ah[2][4], al[2][4];
#pragma unroll
        for (int mt = 0; mt < 2; ++mt) {
            uint32_t ra = pH + (uint32_t)((wm * 32 + mt * 16 + dw) * 48) + arow;
            LDSM_X4(ah[mt][0], ah[mt][1], ah[mt][2], ah[mt][3], ra);
            LDSM_X4(al[mt][0], al[mt][1], al[mt][2], al[mt][3], ra + 6240);
        }
#pragma unroll
        for (int dh = 0; dh < 3; ++dh) {
            const int sl = (dh == 0) ? TN : (dh == 1 ? TC : TP);
            int h = r + 1 - dh;
            if ((unsigned)h < 64u) {
                const int t9 = dh * 3 + dw, j = t9 * 2;
                uint32_t bl0[2], bl1[2];
#pragma unroll
                for (int ntl = 0; ntl < 2; ++ntl)
                    LDSM_X2(bl0[ntl], bl1[ntl],
                            Bb + (uint32_t)(((9 + t9) * 4 + wn * 2 + ntl) * 384) + blo);
#pragma unroll
                for (int mt = 0; mt < 2; ++mt)
#pragma unroll
                    for (int ntl = 0; ntl < 2; ++ntl) {
                        MMA16816(D[sl][mt][ntl], ah[mt][0], ah[mt][1], ah[mt][2], ah[mt][3],
                                 bH0[j + ntl], bH1[j + ntl]);
                        MMA16816(D[sl][mt][ntl], al[mt][0], al[mt][1], al[mt][2], al[mt][3],
                                 bH0[j + ntl], bH1[j + ntl]);
                        MMA16816(D[sl][mt][ntl], ah[mt][0], ah[mt][1], ah[mt][2], ah[mt][3],
                                 bl0[ntl], bl1[ntl]);
                    }
            }
        }
    }
    if (r >= 1) epi_slot(D[TP], racc, b2r, c3r);
    build_row(r + 1, W0, tid, xim, xs, w1s, b1s, As);
}

__global__ void __launch_bounds__(256, 2)
k_conv2(const float* __restrict__ hist,
        const float* __restrict__ c1w, const float* __restrict__ c1b,
        const float* __restrict__ c2b, const float* __restrict__ c3w,
        const float* __restrict__ c3b) {
    extern __shared__ __align__(16) unsigned char smraw[];
    __half* As = (__half*)smraw;               // 12480 halves (2 slots x 2 limbs x 3120)
    __half* Bs = As + 12480;                   // 13824 halves
    float*  xs = (float*)(Bs + 13824);         // 396
    float* w1s = xs + 396;                     // [16][12]
    float* b1s = w1s + 192;                    // 16
    float* b2s = b1s + 16;                     // 32
    float* c3s = b2s + 32;                     // 32
    __shared__ float redp[8][32];

    const int n   = blockIdx.y;
    const int W0  = blockIdx.x * 128;
    const int tid = threadIdx.x;
    const int lane = tid & 31, wid = tid >> 5;
    const int wm = wid >> 1, wn = wid & 1;

    for (int i = tid; i < 192; i += 256)
        w1s[i] = ((i % 12) < 9) ? c1w[(i / 12) * 9 + (i % 12)] : 0.f;
    if (tid < 16) b1s[tid] = c1b[tid];
    if (tid < 32) { b2s[tid] = c2b[tid]; c3s[tid] = c3w[tid]; }
    for (int i = tid; i < 2 * 9 * 32 * 16; i += 256) {
        int k = i & 15, c2 = (i >> 4) & 31, t = i >> 9;
        Bs[(t * 4 + (c2 >> 3)) * 192 + (c2 & 7) * 24 + k] = __ushort_as_half(g_Bt[i]);
    }
    __syncthreads();

    const float* xim = hist + (size_t)n * 64 * WW;
    build_row(0, W0, tid, xim, xs, w1s, b1s, As);

    const uint32_t Bb = smem_u32(Bs);
    const uint32_t blo = (uint32_t)((lane & 7) * 48 + (((lane >> 3) & 1) << 4));
    uint32_t bH0[18], bH1[18];
#pragma unroll
    for (int t = 0; t < 9; ++t)
#pragma unroll
        for (int ntl = 0; ntl < 2; ++ntl) {
            int j = t * 2 + ntl;
            LDSM_X2(bH0[j], bH1[j], Bb + (uint32_t)((t * 4 + wn * 2 + ntl) * 384) + blo);
        }

    float b2r[2][2], c3r[2][2];
#pragma unroll
    for (int ntl = 0; ntl < 2; ++ntl)
#pragma unroll
        for (int lo = 0; lo < 2; ++lo) {
            int c2 = wn * 16 + ntl * 8 + 2 * (lane & 3) + lo;
            b2r[ntl][lo] = b2s[c2];
            c3r[ntl][lo] = c3s[c2];
        }

    const uint32_t Ab = smem_u32(As);
    const uint32_t arow = (uint32_t)((lane & 15) * 48 + ((lane >> 4) << 4));

    float D[3][2][2][4];
#pragma unroll
    for (int s = 0; s < 3; ++s)
#pragma unroll
        for (int mt = 0; mt < 2; ++mt)
#pragma unroll
            for (int ntl = 0; ntl < 2; ++ntl)
#pragma unroll
                for (int i = 0; i < 4; ++i) D[s][mt][ntl][i] = 0.f;
    float racc[4] = {0.f, 0.f, 0.f, 0.f};

    for (int rb = 0; rb < 63; rb += 3) {
        conv_step<1, 0, 2>(rb + 0, D, racc, Ab, Bb, bH0, bH1, wm, wn, arow, blo,
                           b2r, c3r, W0, tid, xim, xs, w1s, b1s, As);
        conv_step<2, 1, 0>(rb + 1, D, racc, Ab, Bb, bH0, bH1, wm, wn, arow, blo,
                           b2r, c3r, W0, tid, xim, xs, w1s, b1s, As);
        conv_step<0, 2, 1>(rb + 2, D, racc, Ab, Bb, bH0, bH1, wm, wn, arow, blo,
                           b2r, c3r, W0, tid, xim, xs, w1s, b1s, As);
    }
    conv_step<1, 0, 2>(63, D, racc, Ab, Bb, bH0, bH1, wm, wn, arow, blo,
                       b2r, c3r, W0, tid, xim, xs, w1s, b1s, As);
    epi_slot(D[0], racc, b2r, c3r);     // h = 63 (slot TC of r=63)

    // quad reduce (fixed order)
#pragma unroll
    for (int j = 0; j < 4; ++j) {
        racc[j] += __shfl_xor_sync(0xffffffffu, racc[j], 1);
        racc[j] += __shfl_xor_sync(0xffffffffu, racc[j], 2);
    }
    if ((lane & 3) == 0) {
        int q = lane >> 2;
#pragma unroll
        for (int j = 0; j < 4; ++j) redp[wid][j * 8 + q] = racc[j];
    }
    __syncthreads();

    if (tid < 128) {
        int wm2 = tid >> 5, idx = tid & 31;
        int j = idx >> 3, q = idx & 7;
        float s = redp[wm2 * 2 + 0][idx] + redp[wm2 * 2 + 1][idx];
        int w = W0 + wm2 * 32 + (j >> 1) * 16 + ((j & 1) << 3) + q;
        g_tsp[n * WW + w] = s * (1.f / 64.f) + c3b[0];
    }
}

// ================= top-k + forced sink/local =================
__global__ void k_topk() {
    const int bh = blockIdx.x;
    __shared__ float v[WW];
    __shared__ unsigned char sel[WW];
    __shared__ float wv[8];
    __shared__ int   wix[8];
    const int tid = threadIdx.x, lane = tid & 31, wid = tid >> 5;

    for (int i = tid; i < WW; i += 256) { v[i] = g_tsp[bh * WW + i]; sel[i] = 0; }
    __syncthreads();
    for (int it = 0; it < NSEL; ++it) {
        float bv = v[tid]; int bi = tid;
        float b2 = v[tid + 256];
        if (b2 > bv) { bv = b2; bi = tid + 256; }
#pragma unroll
        for (int o = 16; o > 0; o >>= 1) {
            float ov = __shfl_xor_sync(0xffffffffu, bv, o);
            int   oi = __shfl_xor_sync(0xffffffffu, bi, o);
            if (ov > bv || (ov == bv && oi < bi)) { bv = ov; bi = oi; }
        }
        if (lane == 0) { wv[wid] = bv; wix[wid] = bi; }
        __syncthreads();
        if (tid == 0) {
            float m = wv[0]; int mi = wix[0];
#pragma unroll
            for (int g = 1; g < 8; ++g)
                if (wv[g] > m || (wv[g] == m && wix[g] < mi)) { m = wv[g]; mi = wix[g]; }
            sel[mi] = 1; v[mi] = -3.0e38f;
        }
        __syncthreads();
    }
    if (tid == 0) {
        for (int i = 0; i < 4; ++i) { sel[i] = 1; sel[WW - 4 + i] = 1; }
        int cnt = 0;
        for (int w = 0; w < WW; ++w)
            if (sel[w]) g_blist[bh * MAXBL + (cnt++)] = w;
        g_bcnt[bh] = cnt;
    }
}

// ================= sparse attention (512 threads / CTA) =================
__global__ void k_attn(const float* __restrict__ kc, const float* __restrict__ vc) {
    const int bh = blockIdx.x;
    const int b = bh >> 5, h = bh & 31, kvh = h >> 2;
    const int tid = threadIdx.x;
    __shared__ float qs[DD];
    __shared__ float sc[MAXBL * BLK];
    __shared__ float redf[512];
    __shared__ float vacc[16][DD];

    const int cnt = g_bcnt[bh];
    const int ntok = cnt * BLK;
    if (tid < DD) qs[tid] = g_q[(b * HH + h) * DD + tid];
    __syncthreads();

    const int wid = tid >> 5, lane = tid & 31;
    const float iscale = 0.08838834764831845f;
    const float4 q4 = *(const float4*)(qs + lane * 4);
    const size_t kvbase = (size_t)(b * KVH + kvh) * SC;

    for (int t = wid; t < ntok; t += 16) {
        int blk = g_blist[bh * MAXBL + (t >> 4)];
        int s = blk * BLK + (t & 15);
        const float* kr = (s == SS - 1) ? (g_kn + (b * KVH + kvh) * DD)
                                        : (kc + (kvbase + s) * DD);
        float4 k4 = ((const float4*)kr)[lane];
        float sum = fmaf(q4.x, k4.x, fmaf(q4.y, k4.y, fmaf(q4.z, k4.z, q4.w * k4.w)));
#pragma unroll
        for (int o = 16; o > 0; o >>= 1) sum += __shfl_xor_sync(0xffffffffu, sum, o);
        if (lane == 0) sc[t] = sum * iscale;
    }
    __syncthreads();

    float m = -3.0e38f;
    for (int t = tid; t < ntok; t += 512) m = fmaxf(m, sc[t]);
    redf[tid] = m; __syncthreads();
    for (int st = 256; st > 0; st >>= 1) {
        if (tid < st) redf[tid] = fmaxf(redf[tid], redf[tid + st]);
        __syncthreads();
    }
    m = redf[0];
    __syncthreads();

    float lp = 0.f;
    for (int t = tid; t < ntok; t += 512) { float p = expf(sc[t] - m); sc[t] = p; lp += p; }
    redf[tid] = lp; __syncthreads();
    for (int st = 256; st > 0; st >>= 1) {
        if (tid < st) redf[tid] += redf[tid + st];
        __syncthreads();
    }
    const float linv = 1.f / redf[0];
    __syncthreads();

    float4 a4 = make_float4(0.f, 0.f, 0.f, 0.f);
    for (int t = wid; t < ntok; t += 16) {
        int blk = g_blist[bh * MAXBL + (t >> 4)];
        int s = blk * BLK + (t & 15);
        const float* vr = (s == SS - 1) ? (g_vn + (b * KVH + kvh) * DD)
                                        : (vc + (kvbase + s) * DD);
        float4 v4 = ((const float4*)vr)[lane];
        float p = sc[t];
        a4.x = fmaf(p, v4.x, a4.x);
        a4.y = fmaf(p, v4.y, a4.y);
        a4.z = fmaf(p, v4.z, a4.z);
        a4.w = fmaf(p, v4.w, a4.w);
    }
    *(float4*)(&vacc[wid][lane * 4]) = a4;
    __syncthreads();

    if (tid < DD) {
        float s = 0.f;
#pragma unroll
        for (int g = 0; g < 16; ++g) s += vacc[g][tid];
        g_ctx[b * HID + h * DD + tid] = s * linv;
    }
}

// ================= Wo GEMV =================
__global__ void k_out(const float* __restrict__ Wo) {
    __shared__ float cs[BB][512];
    const int ks = blockIdx.y, k0 = ks * 512;
    for (int i = threadIdx.x; i < BB * 512; i += 256) {
        int b = i >> 9, kk = i & 511;
        cs[b][kk] = g_ctx[b * HID + k0 + kk];
    }
    __syncthreads();
    const int c = blockIdx.x * 256 + threadIdx.x;
    float a0 = 0.f, a1 = 0.f, a2 = 0.f, a3 = 0.f;
    const float* p = Wo + (size_t)k0 * HID + c;
#pragma unroll 8
    for (int kk = 0; kk < 512; ++kk) {
        float w = p[(size_t)kk * HID];
        a0 = fmaf(cs[0][kk], w, a0);
        a1 = fmaf(cs[1][kk], w, a1);
        a2 = fmaf(cs[2][kk], w, a2);
        a3 = fmaf(cs[3][kk], w, a3);
    }
    g_opart[(ks * BB + 0) * HID + c] = a0;
    g_opart[(ks * BB + 1) * HID + c] = a1;
    g_opart[(ks * BB + 2) * HID + c] = a2;
    g_opart[(ks * BB + 3) * HID + c] = a3;
}

__global__ void k_red_out(float* __restrict__ out) {
    int i = blockIdx.x * 256 + threadIdx.x;
    if (i >= BB * HID) return;
    int b = i / HID, c = i - b * HID;
    float s = 0.f;
#pragma unroll
    for (int ks = 0; ks < KSPL; ++ks) s += g_opart[(ks * BB + b) * HID + c];
    out[i] = s;
}

// ================= host launcher =================
extern "C" void kernel_launch(void* const* d_in, const int* in_sizes, int n_in,
                              void* d_out, int out_size) {
    const float* hid  = (const float*)d_in[0];
    const float* kc   = (const float*)d_in[1];
    const float* vc   = (const float*)d_in[2];
    const float* hist = (const float*)d_in[3];
    const float* cosb = (const float*)d_in[4];
    const float* sinb = (const float*)d_in[5];
    const float* Wq   = (const float*)d_in[6];
    const float* Wk   = (const float*)d_in[7];
    const float* Wv   = (const float*)d_in[8];
    const float* Wo   = (const float*)d_in[9];
    const float* c1w  = (const float*)d_in[10];
    const float* c1b  = (const float*)d_in[11];
    const float* c2w  = (const float*)d_in[12];
    const float* c2b  = (const float*)d_in[13];
    const float* c3w  = (const float*)d_in[14];
    const float* c3b  = (const float*)d_in[15];
    float* out = (float*)d_out;

    cudaFuncSetAttribute(k_conv2, cudaFuncAttributeMaxDynamicSharedMemorySize, CONV2_SMEM);

    k_qkv    <<<dim3(NCOL / 256, KSPL), 256>>>(hid, Wq, Wk, Wv);
    k_rope   <<<(BB * NCOL + 255) / 256, 256>>>(cosb, sinb);
    k_prep   <<<18, 256>>>(c2w);
    k_conv2  <<<dim3(4, BB * HH), 256, CONV2_SMEM>>>(hist, c1w, c1b, c2b, c3w, c3b);
    k_topk   <<<BB * HH, 256>>>();
    k_attn   <<<BB * HH, 512>>>(kc, vc);
    k_out    <<<dim3(HID / 256, KSPL), 256>>>(Wo);
    k_red_out<<<(BB * HID + 255) / 256, 256>>>(out);
}

// round 12
// speedup vs baseline: 2.1043x; 1.0784x over previous
#include <cuda_runtime.h>
#include <cuda_fp16.h>
#include <math.h>
#include <stdint.h>

#define BB    4
#define HH    32
#define KVH   8
#define DD    128
#define HID   4096
#define SC    8191
#define SS    8192
#define WW    512
#define BLK   16
#define NSEL  64
#define MAXBL 80
#define KSPL  8
#define NCOL  (HID + 1024 + 1024)

// ---------------- device scratch ----------------
__device__ float g_part [KSPL * BB * NCOL];
__device__ float g_q    [BB * HH * DD];
__device__ float g_kn   [BB * KVH * DD];
__device__ float g_vn   [BB * KVH * DD];
__device__ float g_tsp  [BB * HH * WW];
__device__ int   g_blist[BB * HH * MAXBL];
__device__ int   g_bcnt [BB * HH];
__device__ float g_ctx  [BB * HID];
__device__ float g_opart[KSPL * BB * HID];
__device__ unsigned short g_Bt[2 * 9 * 32 * 16];   // fp16 limbs of 64*w  [(lb*9+t)*32+c2]*16+c1

// ================= warp-mma helpers =================
__device__ __forceinline__ uint32_t smem_u32(const void* p) {
    uint32_t a;
    asm("{ .reg .u64 t; cvta.to.shared.u64 t, %1; cvt.u32.u64 %0, t; }" : "=r"(a) : "l"(p));
    return a;
}
#define LDSM_X4(r0, r1, r2, r3, addr) \
    asm volatile("ldmatrix.sync.aligned.m8n8.x4.shared.b16 {%0,%1,%2,%3}, [%4];" \
        : "=r"(r0), "=r"(r1), "=r"(r2), "=r"(r3) : "r"(addr))
#define LDSM_X2(r0, r1, addr) \
    asm volatile("ldmatrix.sync.aligned.m8n8.x2.shared.b16 {%0,%1}, [%2];" \
        : "=r"(r0), "=r"(r1) : "r"(addr))
#define MMA16816(d, a0, a1, a2, a3, b0, b1) \
    asm volatile("mma.sync.aligned.m16n8k16.row.col.f32.f16.f16.f32 " \
        "{%0,%1,%2,%3}, {%4,%5,%6,%7}, {%8,%9}, {%0,%1,%2,%3};" \
        : "+f"((d)[0]), "+f"((d)[1]), "+f"((d)[2]), "+f"((d)[3]) \
        : "r"(a0), "r"(a1), "r"(a2), "r"(a3), "r"(b0), "r"(b1))

#define A_PLANE_HALF 3120        // halves per limb plane (130 rows x 24)
#define A_SLOT_B     12480       // bytes per slot (2 limb planes)

// ================= QKV GEMV =================
__global__ void k_qkv(const float* __restrict__ hid, const float* __restrict__ Wq,
                      const float* __restrict__ Wk, const float* __restrict__ Wv) {
    __shared__ float hs[BB][512];
    const int ks = blockIdx.y, k0 = ks * 512;
    for (int i = threadIdx.x; i < BB * 512; i += 256) {
        int b = i >> 9, kk = i & 511;
        hs[b][kk] = hid[b * HID + k0 + kk];
    }
    __syncthreads();
    const int c = blockIdx.x * 256 + threadIdx.x;
    const float* Wm; int ld, cc;
    if (c < HID)              { Wm = Wq; ld = HID;  cc = c; }
    else if (c < HID + 1024)  { Wm = Wk; ld = 1024; cc = c - HID; }
    else                      { Wm = Wv; ld = 1024; cc = c - HID - 1024; }
    float a0 = 0.f, a1 = 0.f, a2 = 0.f, a3 = 0.f;
    const float* p = Wm + (size_t)k0 * ld + cc;
#pragma unroll 8
    for (int kk = 0; kk < 512; ++kk) {
        float w = p[(size_t)kk * ld];
        a0 = fmaf(hs[0][kk], w, a0);
        a1 = fmaf(hs[1][kk], w, a1);
        a2 = fmaf(hs[2][kk], w, a2);
        a3 = fmaf(hs[3][kk], w, a3);
    }
    g_part[((ks * BB + 0) * NCOL) + c] = a0;
    g_part[((ks * BB + 1) * NCOL) + c] = a1;
    g_part[((ks * BB + 2) * NCOL) + c] = a2;
    g_part[((ks * BB + 3) * NCOL) + c] = a3;
}

// ================= reduce + RoPE =================
__global__ void k_rope(const float* __restrict__ cosb, const float* __restrict__ sinb) {
    int i = blockIdx.x * 256 + threadIdx.x;
    if (i >= BB * NCOL) return;
    int b = i / NCOL, c = i - b * NCOL;
    float v = 0.f;
#pragma unroll
    for (int ks = 0; ks < KSPL; ++ks) v += g_part[(ks * BB + b) * NCOL + c];
    if (c < HID + 1024) {
        int d = c & (DD - 1);
        int pair = (d < DD / 2) ? c + DD / 2 : c - DD / 2;
        float pv = 0.f;
#pragma unroll
        for (int ks = 0; ks < KSPL; ++ks) pv += g_part[(ks * BB + b) * NCOL + pair];
        float cs = cosb[b * DD + d], sn = sinb[b * DD + d];
        float rot = (d < DD / 2) ? -pv : pv;
        float out = v * cs + rot * sn;
        if (c < HID) g_q[b * HID + c] = out;
        else         g_kn[b * (KVH * DD) + (c - HID)] = out;
    } else {
        g_vn[b * (KVH * DD) + (c - HID - 1024)] = v;
    }
}

// ====== conv2 weight prep: fp16 limbs of 64*w (all limbs normal-range) =========
__global__ void k_prep(const float* __restrict__ c2w) {
    int idx = blockIdx.x * 256 + threadIdx.x;
    if (idx >= 4608) return;
    int c2 = idx / 144, rem = idx - c2 * 144;
    int c1 = rem / 9, t = rem - c1 * 9;      // t = dh*3+dw
    float a = c2w[idx] * 64.f;
    __half h = __float2half(a);
    __half l = __float2half(a - __half2float(h));
    g_Bt[((0 * 9 + t) * 32 + c2) * 16 + c1] = __half_as_ushort(h);
    g_Bt[((1 * 9 + t) * 32 + c2) * 16 + c1] = __half_as_ushort(l);
}

// ================= mma.sync conv2: CTA = 128 w-pixels of one image ============
// smem: As 2x2x3120 halves (24960B), Bs 13824 halves (27648B),
//       xs ring 4x132 floats, w1s [16][12], b1s 16, b2s 32, c3s 32
#define CONV2_SMEM 55808

// build conv1 row hb into As slot hb&1; 260 units over 256 threads; no barriers
__device__ __forceinline__ void build_row(
    int hb, int W0, int tid,
    const float* xs, const float* w1s, const float* b1s, __half* As)
{
    if (hb >= 64) return;
    __half* dst0 = As + (hb & 1) * 6240;
    const float* xr0 = xs + ((hb - 1) & 3) * 132;
    const float* xr1 = xs + ( hb      & 3) * 132;
    const float* xr2 = xs + ((hb + 1) & 3) * 132;
    for (int u = tid; u < 260; u += 256) {
        int wi  = (u < 130) ? u : (u - 130);
        int c1b = (u < 130) ? 0 : 8;
        bool valid = ((unsigned)(W0 - 1 + wi) < 512u);
        float xv[9];
        xv[0] = xr0[wi]; xv[1] = xr0[wi + 1]; xv[2] = xr0[wi + 2];
        xv[3] = xr1[wi]; xv[4] = xr1[wi + 1]; xv[5] = xr1[wi + 2];
        xv[6] = xr2[wi]; xv[7] = xr2[wi + 1]; xv[8] = xr2[wi + 2];
        uint32_t oh[4], ol[4];
#pragma unroll
        for (int k = 0; k < 8; ++k) {
            int c1 = c1b + k;
            const float* wp = w1s + c1 * 12;
            float s = b1s[c1];
#pragma unroll
            for (int q = 0; q < 9; ++q) s = fmaf(wp[q], xv[q], s);
            float vv = valid ? fmaxf(s, 0.f) : 0.f;
            __half hv = __float2half(vv);
            __half lv = __float2half(vv - __half2float(hv));
            uint32_t hb_ = (uint32_t)__half_as_ushort(hv);
            uint32_t lb_ = (uint32_t)__half_as_ushort(lv);
            if (k & 1) { oh[k >> 1] |= hb_ << 16; ol[k >> 1] |= lb_ << 16; }
            else       { oh[k >> 1]  = hb_;       ol[k >> 1]  = lb_; }
        }
        __half* d = dst0 + wi * 24 + c1b;
        *(uint4*)d = make_uint4(oh[0], oh[1], oh[2], oh[3]);
        *(uint4*)(d + A_PLANE_HALF) = make_uint4(ol[0], ol[1], ol[2], ol[3]);
    }
}

__device__ __forceinline__ void epi_slot(float (&Ds)[2][2][4], float (&racc)[4],
                                         const float (&b2r)[2][2], const float (&c3r)[2][2]) {
#pragma unroll
    for (int mt = 0; mt < 2; ++mt)
#pragma unroll
        for (int ntl = 0; ntl < 2; ++ntl)
#pragma unroll
            for (int i = 0; i < 4; ++i) {
                float d = Ds[mt][ntl][i] * 0.015625f + b2r[ntl][i & 1];
                racc[mt * 2 + (i >> 1)] += fmaxf(d, 0.f) * c3r[ntl][i & 1];
                Ds[mt][ntl][i] = 0.f;
            }
}

template<int TN, int TC, int TP>
__device__ __forceinline__ void conv_step(int r,
    float (&D)[3][2][2][4], float (&racc)[4],
    uint32_t Ab, uint32_t Bb,
    const uint32_t (&bH0)[18], const uint32_t (&bH1)[18],
    int wm, int wn, uint32_t arow, uint32_t blo,
    const float (&b2r)[2][2], const float (&c3r)[2][2],
    int W0, int tid, const float* __restrict__ xim,
    float* xs, const float* w1s, const float* b1s, __half* As)
{
    // phase 1: prefetch image row r+3 into xs ring slot (r+3)&3 (old row r-1 dead)
    {
        const int hh = r + 3;
        float* xd = xs + ((r + 3) & 3) * 132;
        for (int i = tid; i < 132; i += 256) {
            int w = W0 - 2 + i;
            float v = 0.f;
            if (hh < 64 && (unsigned)w < 512u) v = xim[hh * WW + w];
            xd[i] = v;
        }
    }
    // phase 2: MMAs over conv1 row r (As slot r&1)
    const uint32_t pH = Ab + (uint32_t)((r & 1) * A_SLOT_B);
#pragma unroll
    for (int dw = 0; dw < 3; ++dw) {
        uint32_t ah[2][4], al[2][4];
#pragma unroll
        for (int mt = 0; mt < 2; ++mt) {
            uint32_t ra = pH + (uint32_t)((wm * 32 + mt * 16 + dw) * 48) + arow;
            LDSM_X4(ah[mt][0], ah[mt][1], ah[mt][2], ah[mt][3], ra);
            LDSM_X4(al[mt][0], al[mt][1], al[mt][2], al[mt][3], ra + 6240);
        }
#pragma unroll
        for (int dh = 0; dh < 3; ++dh) {
            const int sl = (dh == 0) ? TN : (dh == 1 ? TC : TP);
            int h = r + 1 - dh;
            if ((unsigned)h < 64u) {
                const int t9 = dh * 3 + dw, j = t9 * 2;
                uint32_t bl0[2], bl1[2];
#pragma unroll
                for (int ntl = 0; ntl < 2; ++ntl)
                    LDSM_X2(bl0[ntl], bl1[ntl],
                            Bb + (uint32_t)(((9 + t9) * 4 + wn * 2 + ntl) * 384) + blo);
#pragma unroll
                for (int mt = 0; mt < 2; ++mt)
#pragma unroll
                    for (int ntl = 0; ntl < 2; ++ntl) {
                        MMA16816(D[sl][mt][ntl], ah[mt][0], ah[mt][1], ah[mt][2], ah[mt][3],
                                 bH0[j + ntl], bH1[j + ntl]);
                        MMA16816(D[sl][mt][ntl], al[mt][0], al[mt][1], al[mt][2], al[mt][3],
                                 bH0[j + ntl], bH1[j + ntl]);
                        MMA16816(D[sl][mt][ntl], ah[mt][0], ah[mt][1], ah[mt][2], ah[mt][3],
                                 bl0[ntl], bl1[ntl]);
                    }
            }
        }
    }
    // phase 3: epilogue for h = r-1
    if (r >= 1) epi_slot(D[TP], racc, b2r, c3r);
    // phase 4: build conv1 row r+1 into As slot (r+1)&1
    build_row(r + 1, W0, tid, xs, w1s, b1s, As);
    __syncthreads();   // single barrier per step
}

__global__ void __launch_bounds__(256, 2)
k_conv2(const float* __restrict__ hist,
        const float* __restrict__ c1w, const float* __restrict__ c1b,
        const float* __restrict__ c2b, const float* __restrict__ c3w,
        const float* __restrict__ c3b) {
    extern __shared__ __align__(16) unsigned char smraw[];
    __half* As = (__half*)smraw;               // 12480 halves (2 slots x 2 limbs x 3120)
    __half* Bs = As + 12480;                   // 13824 halves
    float*  xs = (float*)(Bs + 13824);         // ring 4 x 132
    float* w1s = xs + 528;                     // [16][12]
    float* b1s = w1s + 192;                    // 16
    float* b2s = b1s + 16;                     // 32
    float* c3s = b2s + 32;                     // 32
    __shared__ float redp[8][32];

    const int n   = blockIdx.y;
    const int W0  = blockIdx.x * 128;
    const int tid = threadIdx.x;
    const int lane = tid & 31, wid = tid >> 5;
    const int wm = wid >> 1, wn = wid & 1;

    for (int i = tid; i < 192; i += 256)
        w1s[i] = ((i % 12) < 9) ? c1w[(i / 12) * 9 + (i % 12)] : 0.f;
    if (tid < 16) b1s[tid] = c1b[tid];
    if (tid < 32) { b2s[tid] = c2b[tid]; c3s[tid] = c3w[tid]; }
    for (int i = tid; i < 2 * 9 * 32 * 16; i += 256) {
        int k = i & 15, c2 = (i >> 4) & 31, t = i >> 9;
        Bs[(t * 4 + (c2 >> 3)) * 192 + (c2 & 7) * 24 + k] = __ushort_as_half(g_Bt[i]);
    }

    const float* xim = hist + (size_t)n * 64 * WW;
    // prologue: fill xs rows -1..2 (row -1 zeros), then build row 0
    for (int i = tid; i < 4 * 132; i += 256) {
        int rr = i / 132, cc = i - rr * 132;
        int hh = rr - 1;                     // -1..2
        int w = W0 - 2 + cc;
        float v = 0.f;
        if (hh >= 0 && (unsigned)w < 512u) v = xim[hh * WW + w];
        xs[(hh & 3) * 132 + cc] = v;
    }
    __syncthreads();
    build_row(0, W0, tid, xs, w1s, b1s, As);
    __syncthreads();

    const uint32_t Bb = smem_u32(Bs);
    const uint32_t blo = (uint32_t)((lane & 7) * 48 + (((lane >> 3) & 1) << 4));
    uint32_t bH0[18], bH1[18];
#pragma unroll
    for (int t = 0; t < 9; ++t)
#pragma unroll
        for (int ntl = 0; ntl < 2; ++ntl) {
            int j = t * 2 + ntl;
            LDSM_X2(bH0[j], bH1[j], Bb + (uint32_t)((t * 4 + wn * 2 + ntl) * 384) + blo);
        }

    float b2r[2][2], c3r[2][2];
#pragma unroll
    for (int ntl = 0; ntl < 2; ++ntl)
#pragma unroll
        for (int lo = 0; lo < 2; ++lo) {
            int c2 = wn * 16 + ntl * 8 + 2 * (lane & 3) + lo;
            b2r[ntl][lo] = b2s[c2];
            c3r[ntl][lo] = c3s[c2];
        }

    const uint32_t Ab = smem_u32(As);
    const uint32_t arow = (uint32_t)((lane & 15) * 48 + ((lane >> 4) << 4));

    float D[3][2][2][4];
#pragma unroll
    for (int s = 0; s < 3; ++s)
#pragma unroll
        for (int mt = 0; mt < 2; ++mt)
#pragma unroll
            for (int ntl = 0; ntl < 2; ++ntl)
#pragma unroll
                for (int i = 0; i < 4; ++i) D[s][mt][ntl][i] = 0.f;
    float racc[4] = {0.f, 0.f, 0.f, 0.f};

    for (int rb = 0; rb < 63; rb += 3) {
        conv_step<1, 0, 2>(rb + 0, D, racc, Ab, Bb, bH0, bH1, wm, wn, arow, blo,
                           b2r, c3r, W0, tid, xim, xs, w1s, b1s, As);
        conv_step<2, 1, 0>(rb + 1, D, racc, Ab, Bb, bH0, bH1, wm, wn, arow, blo,
                           b2r, c3r, W0, tid, xim, xs, w1s, b1s, As);
        conv_step<0, 2, 1>(rb + 2, D, racc, Ab, Bb, bH0, bH1, wm, wn, arow, blo,
                           b2r, c3r, W0, tid, xim, xs, w1s, b1s, As);
    }
    conv_step<1, 0, 2>(63, D, racc, Ab, Bb, bH0, bH1, wm, wn, arow, blo,
                       b2r, c3r, W0, tid, xim, xs, w1s, b1s, As);
    epi_slot(D[0], racc, b2r, c3r);     // h = 63 (slot TC of r=63)

    // quad reduce (fixed order)
#pragma unroll
    for (int j = 0; j < 4; ++j) {
        racc[j] += __shfl_xor_sync(0xffffffffu, racc[j], 1);
        racc[j] += __shfl_xor_sync(0xffffffffu, racc[j], 2);
    }
    if ((lane & 3) == 0) {
        int q = lane >> 2;
#pragma unroll
        for (int j = 0; j < 4; ++j) redp[wid][j * 8 + q] = racc[j];
    }
    __syncthreads();

    if (tid < 128) {
        int wm2 = tid >> 5, idx = tid & 31;
        int j = idx >> 3, q = idx & 7;
        float s = redp[wm2 * 2 + 0][idx] + redp[wm2 * 2 + 1][idx];
        int w = W0 + wm2 * 32 + (j >> 1) * 16 + ((j & 1) << 3) + q;
        g_tsp[n * WW + w] = s * (1.f / 64.f) + c3b[0];
    }
}

// ================= top-k via exact rank count + forced sink/local =============
__global__ void k_topk() {
    const int bh = blockIdx.x;
    __shared__ float v[WW];
    __shared__ unsigned char sel[WW];
    const int tid = threadIdx.x;

    for (int i = tid; i < WW; i += 256) v[i] = g_tsp[bh * WW + i];
    __syncthreads();

    for (int e = tid; e < WW; e += 256) {
        const float ve = v[e];
        int cnt = 0;
#pragma unroll 8
        for (int j = 0; j < WW; ++j) {
            float vj = v[j];
            cnt += (vj > ve || (vj == ve && j < e)) ? 1 : 0;
        }
        sel[e] = (cnt < NSEL) ? 1 : 0;
    }
    __syncthreads();
    if (tid == 0) {
        for (int i = 0; i < 4; ++i) { sel[i] = 1; sel[WW - 4 + i] = 1; }
        int cnt = 0;
        for (int w = 0; w < WW; ++w)
            if (sel[w]) g_blist[bh * MAXBL + (cnt++)] = w;
        g_bcnt[bh] = cnt;
    }
}

// ================= sparse attention (512 threads / CTA) =================
__global__ void k_attn(const float* __restrict__ kc, const float* __restrict__ vc) {
    const int bh = blockIdx.x;
    const int b = bh >> 5, h = bh & 31, kvh = h >> 2;
    const int tid = threadIdx.x;
    __shared__ float qs[DD];
    __shared__ float sc[MAXBL * BLK];
    __shared__ float redf[512];
    __shared__ float vacc[16][DD];

    const int cnt = g_bcnt[bh];
    const int ntok = cnt * BLK;
    if (tid < DD) qs[tid] = g_q[(b * HH + h) * DD + tid];
    __syncthreads();

    const int wid = tid >> 5, lane = tid & 31;
    const float iscale = 0.08838834764831845f;
    const float4 q4 = *(const float4*)(qs + lane * 4);
    const size_t kvbase = (size_t)(b * KVH + kvh) * SC;

    for (int t = wid; t < ntok; t += 16) {
        int blk = g_blist[bh * MAXBL + (t >> 4)];
        int s = blk * BLK + (t & 15);
        const float* kr = (s == SS - 1) ? (g_kn + (b * KVH + kvh) * DD)
                                        : (kc + (kvbase + s) * DD);
        float4 k4 = ((const float4*)kr)[lane];
        float sum = fmaf(q4.x, k4.x, fmaf(q4.y, k4.y, fmaf(q4.z, k4.z, q4.w * k4.w)));
#pragma unroll
        for (int o = 16; o > 0; o >>= 1) sum += __shfl_xor_sync(0xffffffffu, sum, o);
        if (lane == 0) sc[t] = sum * iscale;
    }
    __syncthreads();

    float m = -3.0e38f;
    for (int t = tid; t < ntok; t += 512) m = fmaxf(m, sc[t]);
    redf[tid] = m; __syncthreads();
    for (int st = 256; st > 0; st >>= 1) {
        if (tid < st) redf[tid] = fmaxf(redf[tid], redf[tid + st]);
        __syncthreads();
    }
    m = redf[0];
    __syncthreads();

    float lp = 0.f;
    for (int t = tid; t < ntok; t += 512) { float p = expf(sc[t] - m); sc[t] = p; lp += p; }
    redf[tid] = lp; __syncthreads();
    for (int st = 256; st > 0; st >>= 1) {
        if (tid < st) redf[tid] += redf[tid + st];
        __syncthreads();
    }
    const float linv = 1.f / redf[0];
    __syncthreads();

    float4 a4 = make_float4(0.f, 0.f, 0.f, 0.f);
    for (int t = wid; t < ntok; t += 16) {
        int blk = g_blist[bh * MAXBL + (t >> 4)];
        int s = blk * BLK + (t & 15);
        const float* vr = (s == SS - 1) ? (g_vn + (b * KVH + kvh) * DD)
                                        : (vc + (kvbase + s) * DD);
        float4 v4 = ((const float4*)vr)[lane];
        float p = sc[t];
        a4.x = fmaf(p, v4.x, a4.x);
        a4.y = fmaf(p, v4.y, a4.y);
        a4.z = fmaf(p, v4.z, a4.z);
        a4.w = fmaf(p, v4.w, a4.w);
    }
    *(float4*)(&vacc[wid][lane * 4]) = a4;
    __syncthreads();

    if (tid < DD) {
        float s = 0.f;
#pragma unroll
        for (int g = 0; g < 16; ++g) s += vacc[g][tid];
        g_ctx[b * HID + h * DD + tid] = s * linv;
    }
}

// ================= Wo GEMV =================
__global__ void k_out(const float* __restrict__ Wo) {
    __shared__ float cs[BB][512];
    const int ks = blockIdx.y, k0 = ks * 512;
    for (int i = threadIdx.x; i < BB * 512; i += 256) {
        int b = i >> 9, kk = i & 511;
        cs[b][kk] = g_ctx[b * HID + k0 + kk];
    }
    __syncthreads();
    const int c = blockIdx.x * 256 + threadIdx.x;
    float a0 = 0.f, a1 = 0.f, a2 = 0.f, a3 = 0.f;
    const float* p = Wo + (size_t)k0 * HID + c;
#pragma unroll 8
    for (int kk = 0; kk < 512; ++kk) {
        float w = p[(size_t)kk * HID];
        a0 = fmaf(cs[0][kk], w, a0);
        a1 = fmaf(cs[1][kk], w, a1);
        a2 = fmaf(cs[2][kk], w, a2);
        a3 = fmaf(cs[3][kk], w, a3);
    }
    g_opart[(ks * BB + 0) * HID + c] = a0;
    g_opart[(ks * BB + 1) * HID + c] = a1;
    g_opart[(ks * BB + 2) * HID + c] = a2;
    g_opart[(ks * BB + 3) * HID + c] = a3;
}

__global__ void k_red_out(float* __restrict__ out) {
    int i = blockIdx.x * 256 + threadIdx.x;
    if (i >= BB * HID) return;
    int b = i / HID, c = i - b * HID;
    float s = 0.f;
#pragma unroll
    for (int ks = 0; ks < KSPL; ++ks) s += g_opart[(ks * BB + b) * HID + c];
    out[i] = s;
}

// ================= host launcher =================
extern "C" void kernel_launch(void* const* d_in, const int* in_sizes, int n_in,
                              void* d_out, int out_size) {
    const float* hid  = (const float*)d_in[0];
    const float* kc   = (const float*)d_in[1];
    const float* vc   = (const float*)d_in[2];
    const float* hist = (const float*)d_in[3];
    const float* cosb = (const float*)d_in[4];
    const float* sinb = (const float*)d_in[5];
    const float* Wq   = (const float*)d_in[6];
    const float* Wk   = (const float*)d_in[7];
    const float* Wv   = (const float*)d_in[8];
    const float* Wo   = (const float*)d_in[9];
    const float* c1w  = (const float*)d_in[10];
    const float* c1b  = (const float*)d_in[11];
    const float* c2w  = (const float*)d_in[12];
    const float* c2b  = (const float*)d_in[13];
    const float* c3w  = (const float*)d_in[14];
    const float* c3b  = (const float*)d_in[15];
    float* out = (float*)d_out;

    cudaFuncSetAttribute(k_conv2, cudaFuncAttributeMaxDynamicSharedMemorySize, CONV2_SMEM);

    k_qkv    <<<dim3(NCOL / 256, KSPL), 256>>>(hid, Wq, Wk, Wv);
    k_rope   <<<(BB * NCOL + 255) / 256, 256>>>(cosb, sinb);
    k_prep   <<<18, 256>>>(c2w);
    k_conv2  <<<dim3(4, BB * HH), 256, CONV2_SMEM>>>(hist, c1w, c1b, c2b, c3w, c3b);
    k_topk   <<<BB * HH, 256>>>();
    k_attn   <<<BB * HH, 512>>>(kc, vc);
    k_out    <<<dim3(HID / 256, KSPL), 256>>>(Wo);
    k_red_out<<<(BB * HID + 255) / 256, 256>>>(out);
}

// round 13
// speedup vs baseline: 2.1252x; 1.0099x over previous
#include <cuda_runtime.h>
#include <cuda_fp16.h>
#include <math.h>
#include <stdint.h>

#define BB    4
#define HH    32
#define KVH   8
#define DD    128
#define HID   4096
#define SC    8191
#define SS    8192
#define WW    512
#define BLK   16
#define NSEL  64
#define MAXBL 80
#define KSPL  8
#define NCOL  (HID + 1024 + 1024)

// ---------------- device scratch ----------------
__device__ float g_part [KSPL * BB * NCOL];
__device__ float g_q    [BB * HH * DD];
__device__ float g_kn   [BB * KVH * DD];
__device__ float g_vn   [BB * KVH * DD];
__device__ float g_tsp  [BB * HH * WW];
__device__ int   g_blist[BB * HH * MAXBL];
__device__ int   g_bcnt [BB * HH];
__device__ float g_ctx  [BB * HID];
__device__ float g_opart[KSPL * BB * HID];
__device__ unsigned short g_Bt[2 * 9 * 32 * 16];   // fp16 limbs of 64*w  [(lb*9+t)*32+c2]*16+c1

// ================= warp-mma helpers =================
__device__ __forceinline__ uint32_t smem_u32(const void* p) {
    uint32_t a;
    asm("{ .reg .u64 t; cvta.to.shared.u64 t, %1; cvt.u32.u64 %0, t; }" : "=r"(a) : "l"(p));
    return a;
}
#define LDSM_X4(r0, r1, r2, r3, addr) \
    asm volatile("ldmatrix.sync.aligned.m8n8.x4.shared.b16 {%0,%1,%2,%3}, [%4];" \
        : "=r"(r0), "=r"(r1), "=r"(r2), "=r"(r3) : "r"(addr))
#define LDSM_X2(r0, r1, addr) \
    asm volatile("ldmatrix.sync.aligned.m8n8.x2.shared.b16 {%0,%1}, [%2];" \
        : "=r"(r0), "=r"(r1) : "r"(addr))
#define MMA16816(d, a0, a1, a2, a3, b0, b1) \
    asm volatile("mma.sync.aligned.m16n8k16.row.col.f32.f16.f16.f32 " \
        "{%0,%1,%2,%3}, {%4,%5,%6,%7}, {%8,%9}, {%0,%1,%2,%3};" \
        : "+f"((d)[0]), "+f"((d)[1]), "+f"((d)[2]), "+f"((d)[3]) \
        : "r"(a0), "r"(a1), "r"(a2), "r"(a3), "r"(b0), "r"(b1))

#define A_PLANE_HALF 3120        // halves per limb plane (130 rows x 24)
#define A_SLOT_B     12480       // bytes per slot (2 limb planes)

// ================= QKV GEMV =================
__global__ void k_qkv(const float* __restrict__ hid, const float* __restrict__ Wq,
                      const float* __restrict__ Wk, const float* __restrict__ Wv) {
    __shared__ float hs[BB][512];
    const int ks = blockIdx.y, k0 = ks * 512;
    for (int i = threadIdx.x; i < BB * 512; i += 256) {
        int b = i >> 9, kk = i & 511;
        hs[b][kk] = hid[b * HID + k0 + kk];
    }
    __syncthreads();
    const int c = blockIdx.x * 256 + threadIdx.x;
    const float* Wm; int ld, cc;
    if (c < HID)              { Wm = Wq; ld = HID;  cc = c; }
    else if (c < HID + 1024)  { Wm = Wk; ld = 1024; cc = c - HID; }
    else                      { Wm = Wv; ld = 1024; cc = c - HID - 1024; }
    float a0 = 0.f, a1 = 0.f, a2 = 0.f, a3 = 0.f;
    const float* p = Wm + (size_t)k0 * ld + cc;
#pragma unroll 8
    for (int kk = 0; kk < 512; ++kk) {
        float w = p[(size_t)kk * ld];
        a0 = fmaf(hs[0][kk], w, a0);
        a1 = fmaf(hs[1][kk], w, a1);
        a2 = fmaf(hs[2][kk], w, a2);
        a3 = fmaf(hs[3][kk], w, a3);
    }
    g_part[((ks * BB + 0) * NCOL) + c] = a0;
    g_part[((ks * BB + 1) * NCOL) + c] = a1;
    g_part[((ks * BB + 2) * NCOL) + c] = a2;
    g_part[((ks * BB + 3) * NCOL) + c] = a3;
}

// ================= reduce + RoPE =================
__global__ void k_rope(const float* __restrict__ cosb, const float* __restrict__ sinb) {
    int i = blockIdx.x * 256 + threadIdx.x;
    if (i >= BB * NCOL) return;
    int b = i / NCOL, c = i - b * NCOL;
    float v = 0.f;
#pragma unroll
    for (int ks = 0; ks < KSPL; ++ks) v += g_part[(ks * BB + b) * NCOL + c];
    if (c < HID + 1024) {
        int d = c & (DD - 1);
        int pair = (d < DD / 2) ? c + DD / 2 : c - DD / 2;
        float pv = 0.f;
#pragma unroll
        for (int ks = 0; ks < KSPL; ++ks) pv += g_part[(ks * BB + b) * NCOL + pair];
        float cs = cosb[b * DD + d], sn = sinb[b * DD + d];
        float rot = (d < DD / 2) ? -pv : pv;
        float out = v * cs + rot * sn;
        if (c < HID) g_q[b * HID + c] = out;
        else         g_kn[b * (KVH * DD) + (c - HID)] = out;
    } else {
        g_vn[b * (KVH * DD) + (c - HID - 1024)] = v;
    }
}

// ====== conv2 weight prep: fp16 limbs of 64*w (all limbs normal-range) =========
__global__ void k_prep(const float* __restrict__ c2w) {
    int idx = blockIdx.x * 256 + threadIdx.x;
    if (idx >= 4608) return;
    int c2 = idx / 144, rem = idx - c2 * 144;
    int c1 = rem / 9, t = rem - c1 * 9;      // t = dh*3+dw
    float a = c2w[idx] * 64.f;
    __half h = __float2half(a);
    __half l = __float2half(a - __half2float(h));
    g_Bt[((0 * 9 + t) * 32 + c2) * 16 + c1] = __half_as_ushort(h);
    g_Bt[((1 * 9 + t) * 32 + c2) * 16 + c1] = __half_as_ushort(l);
}

// ================= mma.sync conv2: CTA = 128 w-pixels of one image ============
#define CONV2_SMEM 55808

// build conv1 row hb into As slot hb&1; 260 units over 256 threads; no barriers
__device__ __forceinline__ void build_row(
    int hb, int W0, int tid,
    const float* xs, const float* w1s, const float* b1s, __half* As)
{
    if (hb >= 64) return;
    __half* dst0 = As + (hb & 1) * 6240;
    const float* xr0 = xs + ((hb - 1) & 3) * 132;
    const float* xr1 = xs + ( hb      & 3) * 132;
    const float* xr2 = xs + ((hb + 1) & 3) * 132;
    for (int u = tid; u < 260; u += 256) {
        int wi  = (u < 130) ? u : (u - 130);
        int c1b = (u < 130) ? 0 : 8;
        bool valid = ((unsigned)(W0 - 1 + wi) < 512u);
        float xv[9];
        xv[0] = xr0[wi]; xv[1] = xr0[wi + 1]; xv[2] = xr0[wi + 2];
        xv[3] = xr1[wi]; xv[4] = xr1[wi + 1]; xv[5] = xr1[wi + 2];
        xv[6] = xr2[wi]; xv[7] = xr2[wi + 1]; xv[8] = xr2[wi + 2];
        uint32_t oh[4], ol[4];
#pragma unroll
        for (int k = 0; k < 8; ++k) {
            int c1 = c1b + k;
            const float* wp = w1s + c1 * 12;
            float s = b1s[c1];
#pragma unroll
            for (int q = 0; q < 9; ++q) s = fmaf(wp[q], xv[q], s);
            float vv = valid ? fmaxf(s, 0.f) : 0.f;
            __half hv = __float2half(vv);
            __half lv = __float2half(vv - __half2float(hv));
            uint32_t hb_ = (uint32_t)__half_as_ushort(hv);
            uint32_t lb_ = (uint32_t)__half_as_ushort(lv);
            if (k & 1) { oh[k >> 1] |= hb_ << 16; ol[k >> 1] |= lb_ << 16; }
            else       { oh[k >> 1]  = hb_;       ol[k >> 1]  = lb_; }
        }
        __half* d = dst0 + wi * 24 + c1b;
        *(uint4*)d = make_uint4(oh[0], oh[1], oh[2], oh[3]);
        *(uint4*)(d + A_PLANE_HALF) = make_uint4(ol[0], ol[1], ol[2], ol[3]);
    }
}

__device__ __forceinline__ void epi_slot(float (&Ds)[2][2][4], float (&racc)[4],
                                         const float (&b2r)[2][2], const float (&c3r)[2][2]) {
#pragma unroll
    for (int mt = 0; mt < 2; ++mt)
#pragma unroll
        for (int ntl = 0; ntl < 2; ++ntl)
#pragma unroll
            for (int i = 0; i < 4; ++i) {
                float d = Ds[mt][ntl][i] * 0.015625f + b2r[ntl][i & 1];
                racc[mt * 2 + (i >> 1)] += fmaxf(d, 0.f) * c3r[ntl][i & 1];
                Ds[mt][ntl][i] = 0.f;
            }
}

template<int TN, int TC, int TP>
__device__ __forceinline__ void conv_step(int r,
    float (&D)[3][2][2][4], float (&racc)[4],
    uint32_t Ab, uint32_t Bb,
    const uint32_t (&bH0)[18], const uint32_t (&bH1)[18],
    int wm, int wn, uint32_t arow, uint32_t blo,
    const float (&b2r)[2][2], const float (&c3r)[2][2],
    int W0, int tid, const float* __restrict__ xim,
    float* xs, const float* w1s, const float* b1s, __half* As)
{
    // phase 1: ISSUE the row r+3 load into a register (completion hidden
    // under the MMA phase; stored to the xs ring in phase 4).
    const int hh = r + 3;
    const bool haspf = (tid < 132);
    float pfv = 0.f;
    if (haspf) {
        int w = W0 - 2 + tid;
        if (hh < 64 && (unsigned)w < 512u) pfv = __ldg(xim + hh * WW + w);
    }

    // phase 2: MMAs over conv1 row r (As slot r&1)
    const uint32_t pH = Ab + (uint32_t)((r & 1) * A_SLOT_B);
#pragma unroll
    for (int dw = 0; dw < 3; ++dw) {
        uint32_t ah[2][4], al[2][4];
#pragma unroll
        for (int mt = 0; mt < 2; ++mt) {
            uint32_t ra = pH + (uint32_t)((wm * 32 + mt * 16 + dw) * 48) + arow;
            LDSM_X4(ah[mt][0], ah[mt][1], ah[mt][2], ah[mt][3], ra);
            LDSM_X4(al[mt][0], al[mt][1], al[mt][2], al[mt][3], ra + 6240);
        }
#pragma unroll
        for (int dh = 0; dh < 3; ++dh) {
            const int sl = (dh == 0) ? TN : (dh == 1 ? TC : TP);
            int h = r + 1 - dh;
            if ((unsigned)h < 64u) {
                const int t9 = dh * 3 + dw, j = t9 * 2;
                uint32_t bl0[2], bl1[2];
#pragma unroll
                for (int ntl = 0; ntl < 2; ++ntl)
                    LDSM_X2(bl0[ntl], bl1[ntl],
                            Bb + (uint32_t)(((9 + t9) * 4 + wn * 2 + ntl) * 384) + blo);
#pragma unroll
                for (int mt = 0; mt < 2; ++mt)
#pragma unroll
                    for (int ntl = 0; ntl < 2; ++ntl) {
                        MMA16816(D[sl][mt][ntl], ah[mt][0], ah[mt][1], ah[mt][2], ah[mt][3],
                                 bH0[j + ntl], bH1[j + ntl]);
                        MMA16816(D[sl][mt][ntl], al[mt][0], al[mt][1], al[mt][2], al[mt][3],
                                 bH0[j + ntl], bH1[j + ntl]);
                        MMA16816(D[sl][mt][ntl], ah[mt][0], ah[mt][1], ah[mt][2], ah[mt][3],
                                 bl0[ntl], bl1[ntl]);
                    }
            }
        }
    }
    // phase 3: epilogue for h = r-1
    if (r >= 1) epi_slot(D[TP], racc, b2r, c3r);
    // phase 4: commit prefetched row, then build conv1 row r+1
    if (haspf) xs[((r + 3) & 3) * 132 + tid] = pfv;
    build_row(r + 1, W0, tid, xs, w1s, b1s, As);
    __syncthreads();   // single barrier per step
}

__global__ void __launch_bounds__(256, 2)
k_conv2(const float* __restrict__ hist,
        const float* __restrict__ c1w, const float* __restrict__ c1b,
        const float* __restrict__ c2b, const float* __restrict__ c3w,
        const float* __restrict__ c3b) {
    extern __shared__ __align__(16) unsigned char smraw[];
    __half* As = (__half*)smraw;               // 12480 halves (2 slots x 2 limbs x 3120)
    __half* Bs = As + 12480;                   // 13824 halves
    float*  xs = (float*)(Bs + 13824);         // ring 4 x 132
    float* w1s = xs + 528;                     // [16][12]
    float* b1s = w1s + 192;                    // 16
    float* b2s = b1s + 16;                     // 32
    float* c3s = b2s + 32;                     // 32
    __shared__ float redp[8][32];

    const int n   = blockIdx.y;
    const int W0  = blockIdx.x * 128;
    const int tid = threadIdx.x;
    const int lane = tid & 31, wid = tid >> 5;
    const int wm = wid >> 1, wn = wid & 1;

    for (int i = tid; i < 192; i += 256)
        w1s[i] = ((i % 12) < 9) ? c1w[(i / 12) * 9 + (i % 12)] : 0.f;
    if (tid < 16) b1s[tid] = c1b[tid];
    if (tid < 32) { b2s[tid] = c2b[tid]; c3s[tid] = c3w[tid]; }
    for (int i = tid; i < 2 * 9 * 32 * 16; i += 256) {
        int k = i & 15, c2 = (i >> 4) & 31, t = i >> 9;
        Bs[(t * 4 + (c2 >> 3)) * 192 + (c2 & 7) * 24 + k] = __ushort_as_half(g_Bt[i]);
    }

    const float* xim = hist + (size_t)n * 64 * WW;
    // prologue: fill xs rows -1..2 (row -1 zeros), then build row 0
    for (int i = tid; i < 4 * 132; i += 256) {
        int rr = i / 132, cc = i - rr * 132;
        int hh = rr - 1;                     // -1..2
        int w = W0 - 2 + cc;
        float v = 0.f;
        if (hh >= 0 && (unsigned)w < 512u) v = xim[hh * WW + w];
        xs[(hh & 3) * 132 + cc] = v;
    }
    __syncthreads();
    build_row(0, W0, tid, xs, w1s, b1s, As);
    __syncthreads();

    const uint32_t Bb = smem_u32(Bs);
    const uint32_t blo = (uint32_t)((lane & 7) * 48 + (((lane >> 3) & 1) << 4));
    uint32_t bH0[18], bH1[18];
#pragma unroll
    for (int t = 0; t < 9; ++t)
#pragma unroll
        for (int ntl = 0; ntl < 2; ++ntl) {
            int j = t * 2 + ntl;
            LDSM_X2(bH0[j], bH1[j], Bb + (uint32_t)((t * 4 + wn * 2 + ntl) * 384) + blo);
        }

    float b2r[2][2], c3r[2][2];
#pragma unroll
    for (int ntl = 0; ntl < 2; ++ntl)
#pragma unroll
        for (int lo = 0; lo < 2; ++lo) {
            int c2 = wn * 16 + ntl * 8 + 2 * (lane & 3) + lo;
            b2r[ntl][lo] = b2s[c2];
            c3r[ntl][lo] = c3s[c2];
        }

    const uint32_t Ab = smem_u32(As);
    const uint32_t arow = (uint32_t)((lane & 15) * 48 + ((lane >> 4) << 4));

    float D[3][2][2][4];
#pragma unroll
    for (int s = 0; s < 3; ++s)
#pragma unroll
        for (int mt = 0; mt < 2; ++mt)
#pragma unroll
            for (int ntl = 0; ntl < 2; ++ntl)
#pragma unroll
                for (int i = 0; i < 4; ++i) D[s][mt][ntl][i] = 0.f;
    float racc[4] = {0.f, 0.f, 0.f, 0.f};

    for (int rb = 0; rb < 63; rb += 3) {
        conv_step<1, 0, 2>(rb + 0, D, racc, Ab, Bb, bH0, bH1, wm, wn, arow, blo,
                           b2r, c3r, W0, tid, xim, xs, w1s, b1s, As);
        conv_step<2, 1, 0>(rb + 1, D, racc, Ab, Bb, bH0, bH1, wm, wn, arow, blo,
                           b2r, c3r, W0, tid, xim, xs, w1s, b1s, As);
        conv_step<0, 2, 1>(rb + 2, D, racc, Ab, Bb, bH0, bH1, wm, wn, arow, blo,
                           b2r, c3r, W0, tid, xim, xs, w1s, b1s, As);
    }
    conv_step<1, 0, 2>(63, D, racc, Ab, Bb, bH0, bH1, wm, wn, arow, blo,
                       b2r, c3r, W0, tid, xim, xs, w1s, b1s, As);
    epi_slot(D[0], racc, b2r, c3r);     // h = 63 (slot TC of r=63)

    // quad reduce (fixed order)
#pragma unroll
    for (int j = 0; j < 4; ++j) {
        racc[j] += __shfl_xor_sync(0xffffffffu, racc[j], 1);
        racc[j] += __shfl_xor_sync(0xffffffffu, racc[j], 2);
    }
    if ((lane & 3) == 0) {
        int q = lane >> 2;
#pragma unroll
        for (int j = 0; j < 4; ++j) redp[wid][j * 8 + q] = racc[j];
    }
    __syncthreads();

    if (tid < 128) {
        int wm2 = tid >> 5, idx = tid & 31;
        int j = idx >> 3, q = idx & 7;
        float s = redp[wm2 * 2 + 0][idx] + redp[wm2 * 2 + 1][idx];
        int w = W0 + wm2 * 32 + (j >> 1) * 16 + ((j & 1) << 3) + q;
        g_tsp[n * WW + w] = s * (1.f / 64.f) + c3b[0];
    }
}

// ================= top-k via exact rank count + forced sink/local =============
__global__ void k_topk() {
    const int bh = blockIdx.x;
    __shared__ float v[WW];
    __shared__ unsigned char sel[WW];
    const int tid = threadIdx.x;

    for (int i = tid; i < WW; i += 256) v[i] = g_tsp[bh * WW + i];
    __syncthreads();

    for (int e = tid; e < WW; e += 256) {
        const float ve = v[e];
        int cnt = 0;
#pragma unroll 8
        for (int j = 0; j < WW; ++j) {
            float vj = v[j];
            cnt += (vj > ve || (vj == ve && j < e)) ? 1 : 0;
        }
        sel[e] = (cnt < NSEL) ? 1 : 0;
    }
    __syncthreads();
    if (tid == 0) {
        for (int i = 0; i < 4; ++i) { sel[i] = 1; sel[WW - 4 + i] = 1; }
        int cnt = 0;
        for (int w = 0; w < WW; ++w)
            if (sel[w]) g_blist[bh * MAXBL + (cnt++)] = w;
        g_bcnt[bh] = cnt;
    }
}

// ================= sparse attention (512 threads / CTA) =================
__global__ void k_attn(const float* __restrict__ kc, const float* __restrict__ vc) {
    const int bh = blockIdx.x;
    const int b = bh >> 5, h = bh & 31, kvh = h >> 2;
    const int tid = threadIdx.x;
    __shared__ float qs[DD];
    __shared__ float sc[MAXBL * BLK];
    __shared__ float redf[512];
    __shared__ float vacc[16][DD];

    const int cnt = g_bcnt[bh];
    const int ntok = cnt * BLK;
    if (tid < DD) qs[tid] = g_q[(b * HH + h) * DD + tid];
    __syncthreads();

    const int wid = tid >> 5, lane = tid & 31;
    const float iscale = 0.08838834764831845f;
    const float4 q4 = *(const float4*)(qs + lane * 4);
    const size_t kvbase = (size_t)(b * KVH + kvh) * SC;

    for (int t = wid; t < ntok; t += 16) {
        int blk = g_blist[bh * MAXBL + (t >> 4)];
        int s = blk * BLK + (t & 15);
        const float* kr = (s == SS - 1) ? (g_kn + (b * KVH + kvh) * DD)
                                        : (kc + (kvbase + s) * DD);
        float4 k4 = ((const float4*)kr)[lane];
        float sum = fmaf(q4.x, k4.x, fmaf(q4.y, k4.y, fmaf(q4.z, k4.z, q4.w * k4.w)));
#pragma unroll
        for (int o = 16; o > 0; o >>= 1) sum += __shfl_xor_sync(0xffffffffu, sum, o);
        if (lane == 0) sc[t] = sum * iscale;
    }
    __syncthreads();

    float m = -3.0e38f;
    for (int t = tid; t < ntok; t += 512) m = fmaxf(m, sc[t]);
    redf[tid] = m; __syncthreads();
    for (int st = 256; st > 0; st >>= 1) {
        if (tid < st) redf[tid] = fmaxf(redf[tid], redf[tid + st]);
        __syncthreads();
    }
    m = redf[0];
    __syncthreads();

    float lp = 0.f;
    for (int t = tid; t < ntok; t += 512) { float p = expf(sc[t] - m); sc[t] = p; lp += p; }
    redf[tid] = lp; __syncthreads();
    for (int st = 256; st > 0; st >>= 1) {
        if (tid < st) redf[tid] += redf[tid + st];
        __syncthreads();
    }
    const float linv = 1.f / redf[0];
    __syncthreads();

    float4 a4 = make_float4(0.f, 0.f, 0.f, 0.f);
    for (int t = wid; t < ntok; t += 16) {
        int blk = g_blist[bh * MAXBL + (t >> 4)];
        int s = blk * BLK + (t & 15);
        const float* vr = (s == SS - 1) ? (g_vn + (b * KVH + kvh) * DD)
                                        : (vc + (kvbase + s) * DD);
        float4 v4 = ((const float4*)vr)[lane];
        float p = sc[t];
        a4.x = fmaf(p, v4.x, a4.x);
        a4.y = fmaf(p, v4.y, a4.y);
        a4.z = fmaf(p, v4.z, a4.z);
        a4.w = fmaf(p, v4.w, a4.w);
    }
    *(float4*)(&vacc[wid][lane * 4]) = a4;
    __syncthreads();

    if (tid < DD) {
        float s = 0.f;
#pragma unroll
        for (int g = 0; g < 16; ++g) s += vacc[g][tid];
        g_ctx[b * HID + h * DD + tid] = s * linv;
    }
}

// ================= Wo GEMV =================
__global__ void k_out(const float* __restrict__ Wo) {
    __shared__ float cs[BB][512];
    const int ks = blockIdx.y, k0 = ks * 512;
    for (int i = threadIdx.x; i < BB * 512; i += 256) {
        int b = i >> 9, kk = i & 511;
        cs[b][kk] = g_ctx[b * HID + k0 + kk];
    }
    __syncthreads();
    const int c = blockIdx.x * 256 + threadIdx.x;
    float a0 = 0.f, a1 = 0.f, a2 = 0.f, a3 = 0.f;
    const float* p = Wo + (size_t)k0 * HID + c;
#pragma unroll 8
    for (int kk = 0; kk < 512; ++kk) {
        float w = p[(size_t)kk * HID];
        a0 = fmaf(cs[0][kk], w, a0);
        a1 = fmaf(cs[1][kk], w, a1);
        a2 = fmaf(cs[2][kk], w, a2);
        a3 = fmaf(cs[3][kk], w, a3);
    }
    g_opart[(ks * BB + 0) * HID + c] = a0;
    g_opart[(ks * BB + 1) * HID + c] = a1;
    g_opart[(ks * BB + 2) * HID + c] = a2;
    g_opart[(ks * BB + 3) * HID + c] = a3;
}

__global__ void k_red_out(float* __restrict__ out) {
    int i = blockIdx.x * 256 + threadIdx.x;
    if (i >= BB * HID) return;
    int b = i / HID, c = i - b * HID;
    float s = 0.f;
#pragma unroll
    for (int ks = 0; ks < KSPL; ++ks) s += g_opart[(ks * BB + b) * HID + c];
    out[i] = s;
}

// ================= host launcher =================
extern "C" void kernel_launch(void* const* d_in, const int* in_sizes, int n_in,
                              void* d_out, int out_size) {
    const float* hid  = (const float*)d_in[0];
    const float* kc   = (const float*)d_in[1];
    const float* vc   = (const float*)d_in[2];
    const float* hist = (const float*)d_in[3];
    const float* cosb = (const float*)d_in[4];
    const float* sinb = (const float*)d_in[5];
    const float* Wq   = (const float*)d_in[6];
    const float* Wk   = (const float*)d_in[7];
    const float* Wv   = (const float*)d_in[8];
    const float* Wo   = (const float*)d_in[9];
    const float* c1w  = (const float*)d_in[10];
    const float* c1b  = (const float*)d_in[11];
    const float* c2w  = (const float*)d_in[12];
    const float* c2b  = (const float*)d_in[13];
    const float* c3w  = (const float*)d_in[14];
    const float* c3b  = (const float*)d_in[15];
    float* out = (float*)d_out;

    cudaFuncSetAttribute(k_conv2, cudaFuncAttributeMaxDynamicSharedMemorySize, CONV2_SMEM);

    k_qkv    <<<dim3(NCOL / 256, KSPL), 256>>>(hid, Wq, Wk, Wv);
    k_rope   <<<(BB * NCOL + 255) / 256, 256>>>(cosb, sinb);
    k_prep   <<<18, 256>>>(c2w);
    k_conv2  <<<dim3(4, BB * HH), 256, CONV2_SMEM>>>(hist, c1w, c1b, c2b, c3w, c3b);
    k_topk   <<<BB * HH, 256>>>();
    k_attn   <<<BB * HH, 512>>>(kc, vc);
    k_out    <<<dim3(HID / 256, KSPL), 256>>>(Wo);
    k_red_out<<<(BB * HID + 255) / 256, 256>>>(out);
}

// round 14
// speedup vs baseline: 2.3537x; 1.1075x over previous
#include <cuda_runtime.h>
#include <cuda_fp16.h>
#include <math.h>
#include <stdint.h>

#define BB    4
#define HH    32
#define KVH   8
#define DD    128
#define HID   4096
#define SC    8191
#define SS    8192
#define WW    512
#define BLK   16
#define NSEL  64
#define MAXBL 80
#define KSPL  16
#define NCOL  (HID + 1024 + 1024)

// ---------------- device scratch ----------------
__device__ float g_part [KSPL * BB * NCOL];
__device__ float g_q    [BB * HH * DD];
__device__ float g_kn   [BB * KVH * DD];
__device__ float g_vn   [BB * KVH * DD];
__device__ float g_tsp  [BB * HH * WW];
__device__ int   g_blist[BB * HH * MAXBL];
__device__ int   g_bcnt [BB * HH];
__device__ float g_ctx  [BB * HID];
__device__ float g_opart[KSPL * BB * HID];
__device__ unsigned short g_Bt[2 * 9 * 32 * 16];   // fp16 limbs of 64*w  [(lb*9+t)*32+c2]*16+c1

// ================= warp-mma helpers =================
__device__ __forceinline__ uint32_t smem_u32(const void* p) {
    uint32_t a;
    asm("{ .reg .u64 t; cvta.to.shared.u64 t, %1; cvt.u32.u64 %0, t; }" : "=r"(a) : "l"(p));
    return a;
}
#define LDSM_X4(r0, r1, r2, r3, addr) \
    asm volatile("ldmatrix.sync.aligned.m8n8.x4.shared.b16 {%0,%1,%2,%3}, [%4];" \
        : "=r"(r0), "=r"(r1), "=r"(r2), "=r"(r3) : "r"(addr))
#define LDSM_X2(r0, r1, addr) \
    asm volatile("ldmatrix.sync.aligned.m8n8.x2.shared.b16 {%0,%1}, [%2];" \
        : "=r"(r0), "=r"(r1) : "r"(addr))
#define MMA16816(d, a0, a1, a2, a3, b0, b1) \
    asm volatile("mma.sync.aligned.m16n8k16.row.col.f32.f16.f16.f32 " \
        "{%0,%1,%2,%3}, {%4,%5,%6,%7}, {%8,%9}, {%0,%1,%2,%3};" \
        : "+f"((d)[0]), "+f"((d)[1]), "+f"((d)[2]), "+f"((d)[3]) \
        : "r"(a0), "r"(a1), "r"(a2), "r"(a3), "r"(b0), "r"(b1))

#define A_PLANE_HALF 3120        // halves per limb plane (130 rows x 24)
#define A_SLOT_B     12480       // bytes per slot (2 limb planes)

// ================= QKV GEMV =================
__global__ void k_qkv(const float* __restrict__ hid, const float* __restrict__ Wq,
                      const float* __restrict__ Wk, const float* __restrict__ Wv) {
    __shared__ float hs[BB][256];
    const int ks = blockIdx.y, k0 = ks * 256;
    for (int i = threadIdx.x; i < BB * 256; i += 256) {
        int b = i >> 8, kk = i & 255;
        hs[b][kk] = hid[b * HID + k0 + kk];
    }
    __syncthreads();
    const int c = blockIdx.x * 256 + threadIdx.x;
    const float* Wm; int ld, cc;
    if (c < HID)              { Wm = Wq; ld = HID;  cc = c; }
    else if (c < HID + 1024)  { Wm = Wk; ld = 1024; cc = c - HID; }
    else                      { Wm = Wv; ld = 1024; cc = c - HID - 1024; }
    float a0 = 0.f, a1 = 0.f, a2 = 0.f, a3 = 0.f;
    const float* p = Wm + (size_t)k0 * ld + cc;
#pragma unroll 8
    for (int kk = 0; kk < 256; ++kk) {
        float w = p[(size_t)kk * ld];
        a0 = fmaf(hs[0][kk], w, a0);
        a1 = fmaf(hs[1][kk], w, a1);
        a2 = fmaf(hs[2][kk], w, a2);
        a3 = fmaf(hs[3][kk], w, a3);
    }
    g_part[((ks * BB + 0) * NCOL) + c] = a0;
    g_part[((ks * BB + 1) * NCOL) + c] = a1;
    g_part[((ks * BB + 2) * NCOL) + c] = a2;
    g_part[((ks * BB + 3) * NCOL) + c] = a3;
}

// ================= reduce + RoPE =================
__global__ void k_rope(const float* __restrict__ cosb, const float* __restrict__ sinb) {
    int i = blockIdx.x * 256 + threadIdx.x;
    if (i >= BB * NCOL) return;
    int b = i / NCOL, c = i - b * NCOL;
    float v = 0.f;
#pragma unroll
    for (int ks = 0; ks < KSPL; ++ks) v += g_part[(ks * BB + b) * NCOL + c];
    if (c < HID + 1024) {
        int d = c & (DD - 1);
        int pair = (d < DD / 2) ? c + DD / 2 : c - DD / 2;
        float pv = 0.f;
#pragma unroll
        for (int ks = 0; ks < KSPL; ++ks) pv += g_part[(ks * BB + b) * NCOL + pair];
        float cs = cosb[b * DD + d], sn = sinb[b * DD + d];
        float rot = (d < DD / 2) ? -pv : pv;
        float out = v * cs + rot * sn;
        if (c < HID) g_q[b * HID + c] = out;
        else         g_kn[b * (KVH * DD) + (c - HID)] = out;
    } else {
        g_vn[b * (KVH * DD) + (c - HID - 1024)] = v;
    }
}

// ====== conv2 weight prep: fp16 limbs of 64*w (all limbs normal-range) =========
__global__ void k_prep(const float* __restrict__ c2w) {
    int idx = blockIdx.x * 256 + threadIdx.x;
    if (idx >= 4608) return;
    int c2 = idx / 144, rem = idx - c2 * 144;
    int c1 = rem / 9, t = rem - c1 * 9;      // t = dh*3+dw
    float a = c2w[idx] * 64.f;
    __half h = __float2half(a);
    __half l = __float2half(a - __half2float(h));
    g_Bt[((0 * 9 + t) * 32 + c2) * 16 + c1] = __half_as_ushort(h);
    g_Bt[((1 * 9 + t) * 32 + c2) * 16 + c1] = __half_as_ushort(l);
}

// ================= mma.sync conv2: CTA = 128 w-pixels of one image ============
// dyn smem: As 4 slots x 2 limbs x 3120 halves = 49920B, Bs 27648B,
//           xs ring 8x132 f = 4224B, w1s/b1s/b2s/c3s = 1088B  -> 82880B
#define CONV2_SMEM 82944

// build conv1 row hb into As slot hb&3; xs ring is 8 slots
__device__ __forceinline__ void build_row(
    int hb, int W0, int tid,
    const float* xs, const float* w1s, const float* b1s, __half* As)
{
    if (hb >= 64) return;
    __half* dst0 = As + (hb & 3) * 6240;
    const float* xr0 = xs + (((hb - 1) + 8) & 7) * 132;
    const float* xr1 = xs + ( hb            & 7) * 132;
    const float* xr2 = xs + ((hb + 1)       & 7) * 132;
    for (int u = tid; u < 260; u += 256) {
        int wi  = (u < 130) ? u : (u - 130);
        int c1b = (u < 130) ? 0 : 8;
        bool valid = ((unsigned)(W0 - 1 + wi) < 512u);
        float xv[9];
        xv[0] = xr0[wi]; xv[1] = xr0[wi + 1]; xv[2] = xr0[wi + 2];
        xv[3] = xr1[wi]; xv[4] = xr1[wi + 1]; xv[5] = xr1[wi + 2];
        xv[6] = xr2[wi]; xv[7] = xr2[wi + 1]; xv[8] = xr2[wi + 2];
        uint32_t oh[4], ol[4];
#pragma unroll
        for (int k = 0; k < 8; ++k) {
            int c1 = c1b + k;
            const float* wp = w1s + c1 * 12;
            float s = b1s[c1];
#pragma unroll
            for (int q = 0; q < 9; ++q) s = fmaf(wp[q], xv[q], s);
            float vv = valid ? fmaxf(s, 0.f) : 0.f;
            __half hv = __float2half(vv);
            __half lv = __float2half(vv - __half2float(hv));
            uint32_t hb_ = (uint32_t)__half_as_ushort(hv);
            uint32_t lb_ = (uint32_t)__half_as_ushort(lv);
            if (k & 1) { oh[k >> 1] |= hb_ << 16; ol[k >> 1] |= lb_ << 16; }
            else       { oh[k >> 1]  = hb_;       ol[k >> 1]  = lb_; }
        }
        __half* d = dst0 + wi * 24 + c1b;
        *(uint4*)d = make_uint4(oh[0], oh[1], oh[2], oh[3]);
        *(uint4*)(d + A_PLANE_HALF) = make_uint4(ol[0], ol[1], ol[2], ol[3]);
    }
}

__device__ __forceinline__ void epi_slot(float (&Ds)[2][2][4], float (&racc)[4],
                                         const float (&b2r)[2][2], const float (&c3r)[2][2]) {
#pragma unroll
    for (int mt = 0; mt < 2; ++mt)
#pragma unroll
        for (int ntl = 0; ntl < 2; ++ntl)
#pragma unroll
            for (int i = 0; i < 4; ++i) {
                float d = Ds[mt][ntl][i] * 0.015625f + b2r[ntl][i & 1];
                racc[mt * 2 + (i >> 1)] += fmaxf(d, 0.f) * c3r[ntl][i & 1];
                Ds[mt][ntl][i] = 0.f;
            }
}

// MMAs for conv1 row rr: dh0 -> slot TN (h=rr+1), dh1 -> TC (h=rr), dh2 -> TP (h=rr-1)
template<int TN, int TC, int TP>
__device__ __forceinline__ void mma_row(int rr,
    float (&D)[3][2][2][4], uint32_t Ab, uint32_t Bb,
    const uint32_t (&bH0)[18], const uint32_t (&bH1)[18],
    int wm, int wn, uint32_t arow, uint32_t blo)
{
    const uint32_t pH = Ab + (uint32_t)((rr & 3) * A_SLOT_B);
#pragma unroll
    for (int dw = 0; dw < 3; ++dw) {
        uint32_t ah[2][4], al[2][4];
#pragma unroll
        for (int mt = 0; mt < 2; ++mt) {
            uint32_t ra = pH + (uint32_t)((wm * 32 + mt * 16 + dw) * 48) + arow;
            LDSM_X4(ah[mt][0], ah[mt][1], ah[mt][2], ah[mt][3], ra);
            LDSM_X4(al[mt][0], al[mt][1], al[mt][2], al[mt][3], ra + 6240);
        }
#pragma unroll
        for (int dh = 0; dh < 3; ++dh) {
            const int sl = (dh == 0) ? TN : (dh == 1 ? TC : TP);
            int h = rr + 1 - dh;
            if ((unsigned)h < 64u) {
                const int t9 = dh * 3 + dw, j = t9 * 2;
                uint32_t bl0[2], bl1[2];
#pragma unroll
                for (int ntl = 0; ntl < 2; ++ntl)
                    LDSM_X2(bl0[ntl], bl1[ntl],
                            Bb + (uint32_t)(((9 + t9) * 4 + wn * 2 + ntl) * 384) + blo);
#pragma unroll
                for (int mt = 0; mt < 2; ++mt)
#pragma unroll
                    for (int ntl = 0; ntl < 2; ++ntl) {
                        MMA16816(D[sl][mt][ntl], ah[mt][0], ah[mt][1], ah[mt][2], ah[mt][3],
                                 bH0[j + ntl], bH1[j + ntl]);
                        MMA16816(D[sl][mt][ntl], al[mt][0], al[mt][1], al[mt][2], al[mt][3],
                                 bH0[j + ntl], bH1[j + ntl]);
                        MMA16816(D[sl][mt][ntl], ah[mt][0], ah[mt][1], ah[mt][2], ah[mt][3],
                                 bl0[ntl], bl1[ntl]);
                    }
            }
        }
    }
}

// double step: rows r (even) and r+1; S0=r%3, S1=(r+1)%3, S2=(r+2)%3
template<int S0, int S1, int S2>
__device__ __forceinline__ void conv_step2(int r,
    float (&D)[3][2][2][4], float (&racc)[4],
    uint32_t Ab, uint32_t Bb,
    const uint32_t (&bH0)[18], const uint32_t (&bH1)[18],
    int wm, int wn, uint32_t arow, uint32_t blo,
    const float (&b2r)[2][2], const float (&c3r)[2][2],
    int W0, int tid, const float* __restrict__ xim,
    float* xs, const float* w1s, const float* b1s, __half* As)
{
    // issue prefetch of image rows r+5, r+6 (committed before builds)
    const bool haspf = (tid < 132);
    float pf0 = 0.f, pf1 = 0.f;
    if (haspf) {
        int w = W0 - 2 + tid;
        bool wok = ((unsigned)w < 512u);
        if (r + 5 < 64 && wok) pf0 = __ldg(xim + (r + 5) * WW + w);
        if (r + 6 < 64 && wok) pf1 = __ldg(xim + (r + 6) * WW + w);
    }
    // row r : dh0->S1 (h=r+1), dh1->S0 (h=r), dh2->S2 (h=r-1)
    mma_row<S1, S0, S2>(r, D, Ab, Bb, bH0, bH1, wm, wn, arow, blo);
    if (r > 0) epi_slot(D[S2], racc, b2r, c3r);          // h = r-1
    // row r+1 : dh0->S2 (h=r+2), dh1->S1 (h=r+1), dh2->S0 (h=r)
    mma_row<S2, S1, S0>(r + 1, D, Ab, Bb, bH0, bH1, wm, wn, arow, blo);
    epi_slot(D[S0], racc, b2r, c3r);                     // h = r
    // commit prefetch, then build conv1 rows r+2, r+3
    if (haspf) {
        xs[((r + 5) & 7) * 132 + tid] = pf0;
        xs[((r + 6) & 7) * 132 + tid] = pf1;
    }
    build_row(r + 2, W0, tid, xs, w1s, b1s, As);
    build_row(r + 3, W0, tid, xs, w1s, b1s, As);
    __syncthreads();   // single barrier per double step
}

__global__ void __launch_bounds__(256, 2)
k_conv2(const float* __restrict__ hist,
        const float* __restrict__ c1w, const float* __restrict__ c1b,
        const float* __restrict__ c2b, const float* __restrict__ c3w,
        const float* __restrict__ c3b) {
    extern __shared__ __align__(16) unsigned char smraw[];
    __half* As = (__half*)smraw;               // 24960 halves (4 slots x 2 limbs x 3120)
    __half* Bs = As + 24960;                   // 13824 halves
    float*  xs = (float*)(Bs + 13824);         // ring 8 x 132
    float* w1s = xs + 1056;                    // [16][12]
    float* b1s = w1s + 192;                    // 16
    float* b2s = b1s + 16;                     // 32
    float* c3s = b2s + 32;                     // 32
    __shared__ float redp[8][32];

    const int n   = blockIdx.y;
    const int W0  = blockIdx.x * 128;
    const int tid = threadIdx.x;
    const int lane = tid & 31, wid = tid >> 5;
    const int wm = wid >> 1, wn = wid & 1;

    for (int i = tid; i < 192; i += 256)
        w1s[i] = ((i % 12) < 9) ? c1w[(i / 12) * 9 + (i % 12)] : 0.f;
    if (tid < 16) b1s[tid] = c1b[tid];
    if (tid < 32) { b2s[tid] = c2b[tid]; c3s[tid] = c3w[tid]; }
    for (int i = tid; i < 2 * 9 * 32 * 16; i += 256) {
        int k = i & 15, c2 = (i >> 4) & 31, t = i >> 9;
        Bs[(t * 4 + (c2 >> 3)) * 192 + (c2 & 7) * 24 + k] = __ushort_as_half(g_Bt[i]);
    }

    const float* xim = hist + (size_t)n * 64 * WW;
    // prologue: fill xs rows -1..4 (row -1 zeros), then build rows 0, 1
    for (int i = tid; i < 6 * 132; i += 256) {
        int rr = i / 132, cc = i - rr * 132;
        int hh = rr - 1;                     // -1..4
        int w = W0 - 2 + cc;
        float v = 0.f;
        if (hh >= 0 && (unsigned)w < 512u) v = xim[hh * WW + w];
        xs[((hh + 8) & 7) * 132 + cc] = v;
    }
    __syncthreads();
    build_row(0, W0, tid, xs, w1s, b1s, As);
    build_row(1, W0, tid, xs, w1s, b1s, As);
    __syncthreads();

    const uint32_t Bb = smem_u32(Bs);
    const uint32_t blo = (uint32_t)((lane & 7) * 48 + (((lane >> 3) & 1) << 4));
    uint32_t bH0[18], bH1[18];
#pragma unroll
    for (int t = 0; t < 9; ++t)
#pragma unroll
        for (int ntl = 0; ntl < 2; ++ntl) {
            int j = t * 2 + ntl;
            LDSM_X2(bH0[j], bH1[j], Bb + (uint32_t)((t * 4 + wn * 2 + ntl) * 384) + blo);
        }

    float b2r[2][2], c3r[2][2];
#pragma unroll
    for (int ntl = 0; ntl < 2; ++ntl)
#pragma unroll
        for (int lo = 0; lo < 2; ++lo) {
            int c2 = wn * 16 + ntl * 8 + 2 * (lane & 3) + lo;
            b2r[ntl][lo] = b2s[c2];
            c3r[ntl][lo] = c3s[c2];
        }

    const uint32_t Ab = smem_u32(As);
    const uint32_t arow = (uint32_t)((lane & 15) * 48 + ((lane >> 4) << 4));

    float D[3][2][2][4];
#pragma unroll
    for (int s = 0; s < 3; ++s)
#pragma unroll
        for (int mt = 0; mt < 2; ++mt)
#pragma unroll
            for (int ntl = 0; ntl < 2; ++ntl)
#pragma unroll
                for (int i = 0; i < 4; ++i) D[s][mt][ntl][i] = 0.f;
    float racc[4] = {0.f, 0.f, 0.f, 0.f};

    for (int rb = 0; rb < 60; rb += 6) {
        conv_step2<0, 1, 2>(rb + 0, D, racc, Ab, Bb, bH0, bH1, wm, wn, arow, blo,
                            b2r, c3r, W0, tid, xim, xs, w1s, b1s, As);
        conv_step2<2, 0, 1>(rb + 2, D, racc, Ab, Bb, bH0, bH1, wm, wn, arow, blo,
                            b2r, c3r, W0, tid, xim, xs, w1s, b1s, As);
        conv_step2<1, 2, 0>(rb + 4, D, racc, Ab, Bb, bH0, bH1, wm, wn, arow, blo,
                            b2r, c3r, W0, tid, xim, xs, w1s, b1s, As);
    }
    conv_step2<0, 1, 2>(60, D, racc, Ab, Bb, bH0, bH1, wm, wn, arow, blo,
                        b2r, c3r, W0, tid, xim, xs, w1s, b1s, As);
    conv_step2<2, 0, 1>(62, D, racc, Ab, Bb, bH0, bH1, wm, wn, arow, blo,
                        b2r, c3r, W0, tid, xim, xs, w1s, b1s, As);
    epi_slot(D[0], racc, b2r, c3r);     // h = 63 (slot 63 % 3 = 0)

    // quad reduce (fixed order)
#pragma unroll
    for (int j = 0; j < 4; ++j) {
        racc[j] += __shfl_xor_sync(0xffffffffu, racc[j], 1);
        racc[j] += __shfl_xor_sync(0xffffffffu, racc[j], 2);
    }
    if ((lane & 3) == 0) {
        int q = lane >> 2;
#pragma unroll
        for (int j = 0; j < 4; ++j) redp[wid][j * 8 + q] = racc[j];
    }
    __syncthreads();

    if (tid < 128) {
        int wm2 = tid >> 5, idx = tid & 31;
        int j = idx >> 3, q = idx & 7;
        float s = redp[wm2 * 2 + 0][idx] + redp[wm2 * 2 + 1][idx];
        int w = W0 + wm2 * 32 + (j >> 1) * 16 + ((j & 1) << 3) + q;
        g_tsp[n * WW + w] = s * (1.f / 64.f) + c3b[0];
    }
}

// ================= top-k via exact rank count + forced sink/local =============
__global__ void k_topk() {
    const int bh = blockIdx.x;
    __shared__ float v[WW];
    __shared__ unsigned char sel[WW];
    const int tid = threadIdx.x;

    for (int i = tid; i < WW; i += 256) v[i] = g_tsp[bh * WW + i];
    __syncthreads();

    for (int e = tid; e < WW; e += 256) {
        const float ve = v[e];
        int cnt = 0;
#pragma unroll 8
        for (int j = 0; j < WW; ++j) {
            float vj = v[j];
            cnt += (vj > ve || (vj == ve && j < e)) ? 1 : 0;
        }
        sel[e] = (cnt < NSEL) ? 1 : 0;
    }
    __syncthreads();
    if (tid == 0) {
        for (int i = 0; i < 4; ++i) { sel[i] = 1; sel[WW - 4 + i] = 1; }
        int cnt = 0;
        for (int w = 0; w < WW; ++w)
            if (sel[w]) g_blist[bh * MAXBL + (cnt++)] = w;
        g_bcnt[bh] = cnt;
    }
}

// ================= sparse attention (512 threads / CTA) =================
__global__ void k_attn(const float* __restrict__ kc, const float* __restrict__ vc) {
    const int bh = blockIdx.x;
    const int b = bh >> 5, h = bh & 31, kvh = h >> 2;
    const int tid = threadIdx.x;
    __shared__ float qs[DD];
    __shared__ float sc[MAXBL * BLK];
    __shared__ float redf[512];
    __shared__ float vacc[16][DD];

    const int cnt = g_bcnt[bh];
    const int ntok = cnt * BLK;
    if (tid < DD) qs[tid] = g_q[(b * HH + h) * DD + tid];
    __syncthreads();

    const int wid = tid >> 5, lane = tid & 31;
    const float iscale = 0.08838834764831845f;
    const float4 q4 = *(const float4*)(qs + lane * 4);
    const size_t kvbase = (size_t)(b * KVH + kvh) * SC;

    for (int t = wid; t < ntok; t += 16) {
        int blk = g_blist[bh * MAXBL + (t >> 4)];
        int s = blk * BLK + (t & 15);
        const float* kr = (s == SS - 1) ? (g_kn + (b * KVH + kvh) * DD)
                                        : (kc + (kvbase + s) * DD);
        float4 k4 = ((const float4*)kr)[lane];
        float sum = fmaf(q4.x, k4.x, fmaf(q4.y, k4.y, fmaf(q4.z, k4.z, q4.w * k4.w)));
#pragma unroll
        for (int o = 16; o > 0; o >>= 1) sum += __shfl_xor_sync(0xffffffffu, sum, o);
        if (lane == 0) sc[t] = sum * iscale;
    }
    __syncthreads();

    float m = -3.0e38f;
    for (int t = tid; t < ntok; t += 512) m = fmaxf(m, sc[t]);
    redf[tid] = m; __syncthreads();
    for (int st = 256; st > 0; st >>= 1) {
        if (tid < st) redf[tid] = fmaxf(redf[tid], redf[tid + st]);
        __syncthreads();
    }
    m = redf[0];
    __syncthreads();

    float lp = 0.f;
    for (int t = tid; t < ntok; t += 512) { float p = expf(sc[t] - m); sc[t] = p; lp += p; }
    redf[tid] = lp; __syncthreads();
    for (int st = 256; st > 0; st >>= 1) {
        if (tid < st) redf[tid] += redf[tid + st];
        __syncthreads();
    }
    const float linv = 1.f / redf[0];
    __syncthreads();

    float4 a4 = make_float4(0.f, 0.f, 0.f, 0.f);
    for (int t = wid; t < ntok; t += 16) {
        int blk = g_blist[bh * MAXBL + (t >> 4)];
        int s = blk * BLK + (t & 15);
        const float* vr = (s == SS - 1) ? (g_vn + (b * KVH + kvh) * DD)
                                        : (vc + (kvbase + s) * DD);
        float4 v4 = ((const float4*)vr)[lane];
        float p = sc[t];
        a4.x = fmaf(p, v4.x, a4.x);
        a4.y = fmaf(p, v4.y, a4.y);
        a4.z = fmaf(p, v4.z, a4.z);
        a4.w = fmaf(p, v4.w, a4.w);
    }
    *(float4*)(&vacc[wid][lane * 4]) = a4;
    __syncthreads();

    if (tid < DD) {
        float s = 0.f;
#pragma unroll
        for (int g = 0; g < 16; ++g) s += vacc[g][tid];
        g_ctx[b * HID + h * DD + tid] = s * linv;
    }
}

// ================= Wo GEMV =================
__global__ void k_out(const float* __restrict__ Wo) {
    __shared__ float cs[BB][256];
    const int ks = blockIdx.y, k0 = ks * 256;
    for (int i = threadIdx.x; i < BB * 256; i += 256) {
        int b = i >> 8, kk = i & 255;
        cs[b][kk] = g_ctx[b * HID + k0 + kk];
    }
    __syncthreads();
    const int c = blockIdx.x * 256 + threadIdx.x;
    float a0 = 0.f, a1 = 0.f, a2 = 0.f, a3 = 0.f;
    const float* p = Wo + (size_t)k0 * HID + c;
#pragma unroll 8
    for (int kk = 0; kk < 256; ++kk) {
        float w = p[(size_t)kk * HID];
        a0 = fmaf(cs[0][kk], w, a0);
        a1 = fmaf(cs[1][kk], w, a1);
        a2 = fmaf(cs[2][kk], w, a2);
        a3 = fmaf(cs[3][kk], w, a3);
    }
    g_opart[(ks * BB + 0) * HID + c] = a0;
    g_opart[(ks * BB + 1) * HID + c] = a1;
    g_opart[(ks * BB + 2) * HID + c] = a2;
    g_opart[(ks * BB + 3) * HID + c] = a3;
}

__global__ void k_red_out(float* __restrict__ out) {
    int i = blockIdx.x * 256 + threadIdx.x;
    if (i >= BB * HID) return;
    int b = i / HID, c = i - b * HID;
    float s = 0.f;
#pragma unroll
    for (int ks = 0; ks < KSPL; ++ks) s += g_opart[(ks * BB + b) * HID + c];
    out[i] = s;
}

// ================= host launcher =================
extern "C" void kernel_launch(void* const* d_in, const int* in_sizes, int n_in,
                              void* d_out, int out_size) {
    const float* hid  = (const float*)d_in[0];
    const float* kc   = (const float*)d_in[1];
    const float* vc   = (const float*)d_in[2];
    const float* hist = (const float*)d_in[3];
    const float* cosb = (const float*)d_in[4];
    const float* sinb = (const float*)d_in[5];
    const float* Wq   = (const float*)d_in[6];
    const float* Wk   = (const float*)d_in[7];
    const float* Wv   = (const float*)d_in[8];
    const float* Wo   = (const float*)d_in[9];
    const float* c1w  = (const float*)d_in[10];
    const float* c1b  = (const float*)d_in[11];
    const float* c2w  = (const float*)d_in[12];
    const float* c2b  = (const float*)d_in[13];
    const float* c3w  = (const float*)d_in[14];
    const float* c3b  = (const float*)d_in[15];
    float* out = (float*)d_out;

    cudaFuncSetAttribute(k_conv2, cudaFuncAttributeMaxDynamicSharedMemorySize, CONV2_SMEM);

    k_qkv    <<<dim3(NCOL / 256, KSPL), 256>>>(hid, Wq, Wk, Wv);
    k_rope   <<<(BB * NCOL + 255) / 256, 256>>>(cosb, sinb);
    k_prep   <<<18, 256>>>(c2w);
    k_conv2  <<<dim3(4, BB * HH), 256, CONV2_SMEM>>>(hist, c1w, c1b, c2b, c3w, c3b);
    k_topk   <<<BB * HH, 256>>>();
    k_attn   <<<BB * HH, 512>>>(kc, vc);
    k_out    <<<dim3(HID / 256, KSPL), 256>>>(Wo);
    k_red_out<<<(BB * HID + 255) / 256, 256>>>(out);
}

// round 15
// speedup vs baseline: 2.6241x; 1.1149x over previous
#include <cuda_runtime.h>
#include <cuda_fp16.h>
#include <math.h>
#include <stdint.h>

#define BB    4
#define HH    32
#define KVH   8
#define DD    128
#define HID   4096
#define SC    8191
#define SS    8192
#define WW    512
#define BLK   16
#define NSEL  64
#define MAXBL 80
#define KSPL  16
#define NCOL  (HID + 1024 + 1024)

// ---------------- device scratch ----------------
__device__ float g_part [KSPL * BB * NCOL];
__device__ float g_q    [BB * HH * DD];
__device__ float g_kn   [BB * KVH * DD];
__device__ float g_vn   [BB * KVH * DD];
__device__ float g_tsp  [BB * HH * WW];
__device__ int   g_blist[BB * HH * MAXBL];
__device__ int   g_bcnt [BB * HH];
__device__ float g_ctx  [BB * HID];
__device__ float g_opart[KSPL * BB * HID];
__device__ unsigned short g_Bt[2 * 9 * 32 * 16];   // fp16 limbs of 64*w  [(lb*9+t)*32+c2]*16+c1

// ================= warp-mma helpers =================
__device__ __forceinline__ uint32_t smem_u32(const void* p) {
    uint32_t a;
    asm("{ .reg .u64 t; cvta.to.shared.u64 t, %1; cvt.u32.u64 %0, t; }" : "=r"(a) : "l"(p));
    return a;
}
#define LDSM_X4(r0, r1, r2, r3, addr) \
    asm volatile("ldmatrix.sync.aligned.m8n8.x4.shared.b16 {%0,%1,%2,%3}, [%4];" \
        : "=r"(r0), "=r"(r1), "=r"(r2), "=r"(r3) : "r"(addr))
#define LDSM_X2(r0, r1, addr) \
    asm volatile("ldmatrix.sync.aligned.m8n8.x2.shared.b16 {%0,%1}, [%2];" \
        : "=r"(r0), "=r"(r1) : "r"(addr))
#define MMA16816(d, a0, a1, a2, a3, b0, b1) \
    asm volatile("mma.sync.aligned.m16n8k16.row.col.f32.f16.f16.f32 " \
        "{%0,%1,%2,%3}, {%4,%5,%6,%7}, {%8,%9}, {%0,%1,%2,%3};" \
        : "+f"((d)[0]), "+f"((d)[1]), "+f"((d)[2]), "+f"((d)[3]) \
        : "r"(a0), "r"(a1), "r"(a2), "r"(a3), "r"(b0), "r"(b1))

#define A_PLANE_HALF 3120        // halves per limb plane (130 rows x 24)
#define A_SLOT_B     12480       // bytes per slot (2 limb planes)

// ================= QKV GEMV =================
__global__ void k_qkv(const float* __restrict__ hid, const float* __restrict__ Wq,
                      const float* __restrict__ Wk, const float* __restrict__ Wv) {
    __shared__ float hs[BB][256];
    const int ks = blockIdx.y, k0 = ks * 256;
    for (int i = threadIdx.x; i < BB * 256; i += 256) {
        int b = i >> 8, kk = i & 255;
        hs[b][kk] = hid[b * HID + k0 + kk];
    }
    __syncthreads();
    const int c = blockIdx.x * 256 + threadIdx.x;
    const float* Wm; int ld, cc;
    if (c < HID)              { Wm = Wq; ld = HID;  cc = c; }
    else if (c < HID + 1024)  { Wm = Wk; ld = 1024; cc = c - HID; }
    else                      { Wm = Wv; ld = 1024; cc = c - HID - 1024; }
    float a0 = 0.f, a1 = 0.f, a2 = 0.f, a3 = 0.f;
    const float* p = Wm + (size_t)k0 * ld + cc;
#pragma unroll 8
    for (int kk = 0; kk < 256; ++kk) {
        float w = p[(size_t)kk * ld];
        a0 = fmaf(hs[0][kk], w, a0);
        a1 = fmaf(hs[1][kk], w, a1);
        a2 = fmaf(hs[2][kk], w, a2);
        a3 = fmaf(hs[3][kk], w, a3);
    }
    g_part[((ks * BB + 0) * NCOL) + c] = a0;
    g_part[((ks * BB + 1) * NCOL) + c] = a1;
    g_part[((ks * BB + 2) * NCOL) + c] = a2;
    g_part[((ks * BB + 3) * NCOL) + c] = a3;
}

// ================= reduce + RoPE =================
__global__ void k_rope(const float* __restrict__ cosb, const float* __restrict__ sinb) {
    int i = blockIdx.x * 256 + threadIdx.x;
    if (i >= BB * NCOL) return;
    int b = i / NCOL, c = i - b * NCOL;
    float v = 0.f;
#pragma unroll
    for (int ks = 0; ks < KSPL; ++ks) v += g_part[(ks * BB + b) * NCOL + c];
    if (c < HID + 1024) {
        int d = c & (DD - 1);
        int pair = (d < DD / 2) ? c + DD / 2 : c - DD / 2;
        float pv = 0.f;
#pragma unroll
        for (int ks = 0; ks < KSPL; ++ks) pv += g_part[(ks * BB + b) * NCOL + pair];
        float cs = cosb[b * DD + d], sn = sinb[b * DD + d];
        float rot = (d < DD / 2) ? -pv : pv;
        float out = v * cs + rot * sn;
        if (c < HID) g_q[b * HID + c] = out;
        else         g_kn[b * (KVH * DD) + (c - HID)] = out;
    } else {
        g_vn[b * (KVH * DD) + (c - HID - 1024)] = v;
    }
}

// ====== conv2 weight prep: fp16 limbs of 64*w (all limbs normal-range) =========
__global__ void k_prep(const float* __restrict__ c2w) {
    int idx = blockIdx.x * 256 + threadIdx.x;
    if (idx >= 4608) return;
    int c2 = idx / 144, rem = idx - c2 * 144;
    int c1 = rem / 9, t = rem - c1 * 9;      // t = dh*3+dw
    float a = c2w[idx] * 64.f;
    __half h = __float2half(a);
    __half l = __float2half(a - __half2float(h));
    g_Bt[((0 * 9 + t) * 32 + c2) * 16 + c1] = __half_as_ushort(h);
    g_Bt[((1 * 9 + t) * 32 + c2) * 16 + c1] = __half_as_ushort(l);
}

// ================= mma.sync conv2: CTA = 128 w-pixels of one image ============
#define CONV2_SMEM 55808

// build conv1 row hb into As slot hb&1; 260 units over 256 threads; no barriers
__device__ __forceinline__ void build_row(
    int hb, int W0, int tid,
    const float* xs, const float* w1s, const float* b1s, __half* As)
{
    if (hb >= 64) return;
    __half* dst0 = As + (hb & 1) * 6240;
    const float* xr0 = xs + ((hb - 1) & 3) * 132;
    const float* xr1 = xs + ( hb      & 3) * 132;
    const float* xr2 = xs + ((hb + 1) & 3) * 132;
    for (int u = tid; u < 260; u += 256) {
        int wi  = (u < 130) ? u : (u - 130);
        int c1b = (u < 130) ? 0 : 8;
        bool valid = ((unsigned)(W0 - 1 + wi) < 512u);
        float xv[9];
        xv[0] = xr0[wi]; xv[1] = xr0[wi + 1]; xv[2] = xr0[wi + 2];
        xv[3] = xr1[wi]; xv[4] = xr1[wi + 1]; xv[5] = xr1[wi + 2];
        xv[6] = xr2[wi]; xv[7] = xr2[wi + 1]; xv[8] = xr2[wi + 2];
        uint32_t oh[4], ol[4];
#pragma unroll
        for (int k = 0; k < 8; ++k) {
            int c1 = c1b + k;
            const float* wp = w1s + c1 * 12;
            float s = b1s[c1];
#pragma unroll
            for (int q = 0; q < 9; ++q) s = fmaf(wp[q], xv[q], s);
            float vv = valid ? fmaxf(s, 0.f) : 0.f;
            __half hv = __float2half(vv);
            __half lv = __float2half(vv - __half2float(hv));
            uint32_t hb_ = (uint32_t)__half_as_ushort(hv);
            uint32_t lb_ = (uint32_t)__half_as_ushort(lv);
            if (k & 1) { oh[k >> 1] |= hb_ << 16; ol[k >> 1] |= lb_ << 16; }
            else       { oh[k >> 1]  = hb_;       ol[k >> 1]  = lb_; }
        }
        __half* d = dst0 + wi * 24 + c1b;
        *(uint4*)d = make_uint4(oh[0], oh[1], oh[2], oh[3]);
        *(uint4*)(d + A_PLANE_HALF) = make_uint4(ol[0], ol[1], ol[2], ol[3]);
    }
}

__device__ __forceinline__ void epi_slot(float (&Ds)[2][2][4], float (&racc)[4],
                                         const float (&b2r)[2][2], const float (&c3r)[2][2]) {
#pragma unroll
    for (int mt = 0; mt < 2; ++mt)
#pragma unroll
        for (int ntl = 0; ntl < 2; ++ntl)
#pragma unroll
            for (int i = 0; i < 4; ++i) {
                float d = Ds[mt][ntl][i] * 0.015625f + b2r[ntl][i & 1];
                racc[mt * 2 + (i >> 1)] += fmaxf(d, 0.f) * c3r[ntl][i & 1];
                Ds[mt][ntl][i] = 0.f;
            }
}

template<int TN, int TC, int TP>
__device__ __forceinline__ void conv_step(int r,
    float (&D)[3][2][2][4], float (&racc)[4],
    uint32_t Ab, uint32_t Bb,
    const uint32_t (&bH0)[18], const uint32_t (&bH1)[18],
    int wm, int wn, uint32_t arow, uint32_t blo,
    const float (&b2r)[2][2], const float (&c3r)[2][2],
    int W0, int tid, const float* __restrict__ xim,
    float* xs, const float* w1s, const float* b1s, __half* As)
{
    // phase 1: ISSUE the row r+3 load into a register
    const int hh = r + 3;
    const bool haspf = (tid < 132);
    float pfv = 0.f;
    if (haspf) {
        int w = W0 - 2 + tid;
        if (hh < 64 && (unsigned)w < 512u) pfv = __ldg(xim + hh * WW + w);
    }

    // phase 2: MMAs over conv1 row r (As slot r&1)
    const uint32_t pH = Ab + (uint32_t)((r & 1) * A_SLOT_B);
#pragma unroll
    for (int dw = 0; dw < 3; ++dw) {
        uint32_t ah[2][4], al[2][4];
#pragma unroll
        for (int mt = 0; mt < 2; ++mt) {
            uint32_t ra = pH + (uint32_t)((wm * 32 + mt * 16 + dw) * 48) + arow;
            LDSM_X4(ah[mt][0], ah[mt][1], ah[mt][2], ah[mt][3], ra);
            LDSM_X4(al[mt][0], al[mt][1], al[mt][2], al[mt][3], ra + 6240);
        }
#pragma unroll
        for (int dh = 0; dh < 3; ++dh) {
            const int sl = (dh == 0) ? TN : (dh == 1 ? TC : TP);
            int h = r + 1 - dh;
            if ((unsigned)h < 64u) {
                const int t9 = dh * 3 + dw, j = t9 * 2;
                uint32_t bl0[2], bl1[2];
#pragma unroll
                for (int ntl = 0; ntl < 2; ++ntl)
                    LDSM_X2(bl0[ntl], bl1[ntl],
                            Bb + (uint32_t)(((9 + t9) * 4 + wn * 2 + ntl) * 384) + blo);
#pragma unroll
                for (int mt = 0; mt < 2; ++mt)
#pragma unroll
                    for (int ntl = 0; ntl < 2; ++ntl) {
                        MMA16816(D[sl][mt][ntl], ah[mt][0], ah[mt][1], ah[mt][2], ah[mt][3],
                                 bH0[j + ntl], bH1[j + ntl]);
                        MMA16816(D[sl][mt][ntl], al[mt][0], al[mt][1], al[mt][2], al[mt][3],
                                 bH0[j + ntl], bH1[j + ntl]);
                        MMA16816(D[sl][mt][ntl], ah[mt][0], ah[mt][1], ah[mt][2], ah[mt][3],
                                 bl0[ntl], bl1[ntl]);
                    }
            }
        }
    }
    // phase 3: epilogue for h = r-1
    if (r >= 1) epi_slot(D[TP], racc, b2r, c3r);
    // phase 4: commit prefetched row, then build conv1 row r+1
    if (haspf) xs[((r + 3) & 3) * 132 + tid] = pfv;
    build_row(r + 1, W0, tid, xs, w1s, b1s, As);
    __syncthreads();   // single barrier per step
}

__global__ void __launch_bounds__(256, 2)
k_conv2(const float* __restrict__ hist,
        const float* __restrict__ c1w, const float* __restrict__ c1b,
        const float* __restrict__ c2b, const float* __restrict__ c3w,
        const float* __restrict__ c3b) {
    extern __shared__ __align__(16) unsigned char smraw[];
    __half* As = (__half*)smraw;               // 12480 halves (2 slots x 2 limbs x 3120)
    __half* Bs = As + 12480;                   // 13824 halves
    float*  xs = (float*)(Bs + 13824);         // ring 4 x 132
    float* w1s = xs + 528;                     // [16][12]
    float* b1s = w1s + 192;                    // 16
    float* b2s = b1s + 16;                     // 32
    float* c3s = b2s + 32;                     // 32
    __shared__ float redp[8][32];

    const int n   = blockIdx.y;
    const int W0  = blockIdx.x * 128;
    const int tid = threadIdx.x;
    const int lane = tid & 31, wid = tid >> 5;
    const int wm = wid >> 1, wn = wid & 1;

    for (int i = tid; i < 192; i += 256)
        w1s[i] = ((i % 12) < 9) ? c1w[(i / 12) * 9 + (i % 12)] : 0.f;
    if (tid < 16) b1s[tid] = c1b[tid];
    if (tid < 32) { b2s[tid] = c2b[tid]; c3s[tid] = c3w[tid]; }
    for (int i = tid; i < 2 * 9 * 32 * 16; i += 256) {
        int k = i & 15, c2 = (i >> 4) & 31, t = i >> 9;
        Bs[(t * 4 + (c2 >> 3)) * 192 + (c2 & 7) * 24 + k] = __ushort_as_half(g_Bt[i]);
    }

    const float* xim = hist + (size_t)n * 64 * WW;
    for (int i = tid; i < 4 * 132; i += 256) {
        int rr = i / 132, cc = i - rr * 132;
        int hh = rr - 1;                     // -1..2
        int w = W0 - 2 + cc;
        float v = 0.f;
        if (hh >= 0 && (unsigned)w < 512u) v = xim[hh * WW + w];
        xs[(hh & 3) * 132 + cc] = v;
    }
    __syncthreads();
    build_row(0, W0, tid, xs, w1s, b1s, As);
    __syncthreads();

    const uint32_t Bb = smem_u32(Bs);
    const uint32_t blo = (uint32_t)((lane & 7) * 48 + (((lane >> 3) & 1) << 4));
    uint32_t bH0[18], bH1[18];
#pragma unroll
    for (int t = 0; t < 9; ++t)
#pragma unroll
        for (int ntl = 0; ntl < 2; ++ntl) {
            int j = t * 2 + ntl;
            LDSM_X2(bH0[j], bH1[j], Bb + (uint32_t)((t * 4 + wn * 2 + ntl) * 384) + blo);
        }

    float b2r[2][2], c3r[2][2];
#pragma unroll
    for (int ntl = 0; ntl < 2; ++ntl)
#pragma unroll
        for (int lo = 0; lo < 2; ++lo) {
            int c2 = wn * 16 + ntl * 8 + 2 * (lane & 3) + lo;
            b2r[ntl][lo] = b2s[c2];
            c3r[ntl][lo] = c3s[c2];
        }

    const uint32_t Ab = smem_u32(As);
    const uint32_t arow = (uint32_t)((lane & 15) * 48 + ((lane >> 4) << 4));

    float D[3][2][2][4];
#pragma unroll
    for (int s = 0; s < 3; ++s)
#pragma unroll
        for (int mt = 0; mt < 2; ++mt)
#pragma unroll
            for (int ntl = 0; ntl < 2; ++ntl)
#pragma unroll
                for (int i = 0; i < 4; ++i) D[s][mt][ntl][i] = 0.f;
    float racc[4] = {0.f, 0.f, 0.f, 0.f};

    for (int rb = 0; rb < 63; rb += 3) {
        conv_step<1, 0, 2>(rb + 0, D, racc, Ab, Bb, bH0, bH1, wm, wn, arow, blo,
                           b2r, c3r, W0, tid, xim, xs, w1s, b1s, As);
        conv_step<2, 1, 0>(rb + 1, D, racc, Ab, Bb, bH0, bH1, wm, wn, arow, blo,
                           b2r, c3r, W0, tid, xim, xs, w1s, b1s, As);
        conv_step<0, 2, 1>(rb + 2, D, racc, Ab, Bb, bH0, bH1, wm, wn, arow, blo,
                           b2r, c3r, W0, tid, xim, xs, w1s, b1s, As);
    }
    conv_step<1, 0, 2>(63, D, racc, Ab, Bb, bH0, bH1, wm, wn, arow, blo,
                       b2r, c3r, W0, tid, xim, xs, w1s, b1s, As);
    epi_slot(D[0], racc, b2r, c3r);     // h = 63 (slot TC of r=63)

    // quad reduce (fixed order)
#pragma unroll
    for (int j = 0; j < 4; ++j) {
        racc[j] += __shfl_xor_sync(0xffffffffu, racc[j], 1);
        racc[j] += __shfl_xor_sync(0xffffffffu, racc[j], 2);
    }
    if ((lane & 3) == 0) {
        int q = lane >> 2;
#pragma unroll
        for (int j = 0; j < 4; ++j) redp[wid][j * 8 + q] = racc[j];
    }
    __syncthreads();

    if (tid < 128) {
        int wm2 = tid >> 5, idx = tid & 31;
        int j = idx >> 3, q = idx & 7;
        float s = redp[wm2 * 2 + 0][idx] + redp[wm2 * 2 + 1][idx];
        int w = W0 + wm2 * 32 + (j >> 1) * 16 + ((j & 1) << 3) + q;
        g_tsp[n * WW + w] = s * (1.f / 64.f) + c3b[0];
    }
}

// ================= top-k via exact rank count + forced sink/local =============
__global__ void k_topk() {
    const int bh = blockIdx.x;
    __shared__ float v[WW];
    __shared__ unsigned char sel[WW];
    const int tid = threadIdx.x;

    for (int i = tid; i < WW; i += 256) v[i] = g_tsp[bh * WW + i];
    __syncthreads();

    for (int e = tid; e < WW; e += 256) {
        const float ve = v[e];
        int cnt = 0;
#pragma unroll 8
        for (int j = 0; j < WW; ++j) {
            float vj = v[j];
            cnt += (vj > ve || (vj == ve && j < e)) ? 1 : 0;
        }
        sel[e] = (cnt < NSEL) ? 1 : 0;
    }
    __syncthreads();
    if (tid == 0) {
        for (int i = 0; i < 4; ++i) { sel[i] = 1; sel[WW - 4 + i] = 1; }
        int cnt = 0;
        for (int w = 0; w < WW; ++w)
            if (sel[w]) g_blist[bh * MAXBL + (cnt++)] = w;
        g_bcnt[bh] = cnt;
    }
}

// ================= sparse attention (512 threads / CTA) =================
__global__ void k_attn(const float* __restrict__ kc, const float* __restrict__ vc) {
    const int bh = blockIdx.x;
    const int b = bh >> 5, h = bh & 31, kvh = h >> 2;
    const int tid = threadIdx.x;
    __shared__ float qs[DD];
    __shared__ float sc[MAXBL * BLK];
    __shared__ float redf[512];
    __shared__ float vacc[16][DD];

    const int cnt = g_bcnt[bh];
    const int ntok = cnt * BLK;
    if (tid < DD) qs[tid] = g_q[(b * HH + h) * DD + tid];
    __syncthreads();

    const int wid = tid >> 5, lane = tid & 31;
    const float iscale = 0.08838834764831845f;
    const float4 q4 = *(const float4*)(qs + lane * 4);
    const size_t kvbase = (size_t)(b * KVH + kvh) * SC;

    for (int t = wid; t < ntok; t += 16) {
        int blk = g_blist[bh * MAXBL + (t >> 4)];
        int s = blk * BLK + (t & 15);
        const float* kr = (s == SS - 1) ? (g_kn + (b * KVH + kvh) * DD)
                                        : (kc + (kvbase + s) * DD);
        float4 k4 = ((const float4*)kr)[lane];
        float sum = fmaf(q4.x, k4.x, fmaf(q4.y, k4.y, fmaf(q4.z, k4.z, q4.w * k4.w)));
#pragma unroll
        for (int o = 16; o > 0; o >>= 1) sum += __shfl_xor_sync(0xffffffffu, sum, o);
        if (lane == 0) sc[t] = sum * iscale;
    }
    __syncthreads();

    float m = -3.0e38f;
    for (int t = tid; t < ntok; t += 512) m = fmaxf(m, sc[t]);
    redf[tid] = m; __syncthreads();
    for (int st = 256; st > 0; st >>= 1) {
        if (tid < st) redf[tid] = fmaxf(redf[tid], redf[tid + st]);
        __syncthreads();
    }
    m = redf[0];
    __syncthreads();

    float lp = 0.f;
    for (int t = tid; t < ntok; t += 512) { float p = expf(sc[t] - m); sc[t] = p; lp += p; }
    redf[tid] = lp; __syncthreads();
    for (int st = 256; st > 0; st >>= 1) {
        if (tid < st) redf[tid] += redf[tid + st];
        __syncthreads();
    }
    const float linv = 1.f / redf[0];
    __syncthreads();

    float4 a4 = make_float4(0.f, 0.f, 0.f, 0.f);
    for (int t = wid; t < ntok; t += 16) {
        int blk = g_blist[bh * MAXBL + (t >> 4)];
        int s = blk * BLK + (t & 15);
        const float* vr = (s == SS - 1) ? (g_vn + (b * KVH + kvh) * DD)
                                        : (vc + (kvbase + s) * DD);
        float4 v4 = ((const float4*)vr)[lane];
        float p = sc[t];
        a4.x = fmaf(p, v4.x, a4.x);
        a4.y = fmaf(p, v4.y, a4.y);
        a4.z = fmaf(p, v4.z, a4.z);
        a4.w = fmaf(p, v4.w, a4.w);
    }
    *(float4*)(&vacc[wid][lane * 4]) = a4;
    __syncthreads();

    if (tid < DD) {
        float s = 0.f;
#pragma unroll
        for (int g = 0; g < 16; ++g) s += vacc[g][tid];
        g_ctx[b * HID + h * DD + tid] = s * linv;
    }
}

// ================= Wo GEMV =================
__global__ void k_out(const float* __restrict__ Wo) {
    __shared__ float cs[BB][256];
    const int ks = blockIdx.y, k0 = ks * 256;
    for (int i = threadIdx.x; i < BB * 256; i += 256) {
        int b = i >> 8, kk = i & 255;
        cs[b][kk] = g_ctx[b * HID + k0 + kk];
    }
    __syncthreads();
    const int c = blockIdx.x * 256 + threadIdx.x;
    float a0 = 0.f, a1 = 0.f, a2 = 0.f, a3 = 0.f;
    const float* p = Wo + (size_t)k0 * HID + c;
#pragma unroll 8
    for (int kk = 0; kk < 256; ++kk) {
        float w = p[(size_t)kk * HID];
        a0 = fmaf(cs[0][kk], w, a0);
        a1 = fmaf(cs[1][kk], w, a1);
        a2 = fmaf(cs[2][kk], w, a2);
        a3 = fmaf(cs[3][kk], w, a3);
    }
    g_opart[(ks * BB + 0) * HID + c] = a0;
    g_opart[(ks * BB + 1) * HID + c] = a1;
    g_opart[(ks * BB + 2) * HID + c] = a2;
    g_opart[(ks * BB + 3) * HID + c] = a3;
}

__global__ void k_red_out(float* __restrict__ out) {
    int i = blockIdx.x * 256 + threadIdx.x;
    if (i >= BB * HID) return;
    int b = i / HID, c = i - b * HID;
    float s = 0.f;
#pragma unroll
    for (int ks = 0; ks < KSPL; ++ks) s += g_opart[(ks * BB + b) * HID + c];
    out[i] = s;
}

// ================= host launcher (forked graph) =================
extern "C" void kernel_launch(void* const* d_in, const int* in_sizes, int n_in,
                              void* d_out, int out_size) {
    const float* hid  = (const float*)d_in[0];
    const float* kc   = (const float*)d_in[1];
    const float* vc   = (const float*)d_in[2];
    const float* hist = (const float*)d_in[3];
    const float* cosb = (const float*)d_in[4];
    const float* sinb = (const float*)d_in[5];
    const float* Wq   = (const float*)d_in[6];
    const float* Wk   = (const float*)d_in[7];
    const float* Wv   = (const float*)d_in[8];
    const float* Wo   = (const float*)d_in[9];
    const float* c1w  = (const float*)d_in[10];
    const float* c1b  = (const float*)d_in[11];
    const float* c2w  = (const float*)d_in[12];
    const float* c2b  = (const float*)d_in[13];
    const float* c3w  = (const float*)d_in[14];
    const float* c3b  = (const float*)d_in[15];
    float* out = (float*)d_out;

    cudaFuncSetAttribute(k_conv2, cudaFuncAttributeMaxDynamicSharedMemorySize, CONV2_SMEM);

    // fork: conv branch on s2, qkv branch on the (capturable) default stream
    cudaStream_t s2;
    cudaEvent_t e0, e1;
    cudaStreamCreateWithFlags(&s2, cudaStreamNonBlocking);
    cudaEventCreateWithFlags(&e0, cudaEventDisableTiming);
    cudaEventCreateWithFlags(&e1, cudaEventDisableTiming);

    cudaEventRecord(e0, 0);
    cudaStreamWaitEvent(s2, e0, 0);

    // branch A (s2): conv pipeline
    k_prep <<<18, 256, 0, s2>>>(c2w);
    k_conv2<<<dim3(4, BB * HH), 256, CONV2_SMEM, s2>>>(hist, c1w, c1b, c2b, c3w, c3b);
    k_topk <<<BB * HH, 256, 0, s2>>>();
    cudaEventRecord(e1, s2);

    // branch B (default): qkv + rope
    k_qkv <<<dim3(NCOL / 256, KSPL), 256>>>(hid, Wq, Wk, Wv);
    k_rope<<<(BB * NCOL + 255) / 256, 256>>>(cosb, sinb);

    // join, then tail
    cudaStreamWaitEvent(0, e1, 0);
    k_attn   <<<BB * HH, 512>>>(kc, vc);
    k_out    <<<dim3(HID / 256, KSPL), 256>>>(Wo);
    k_red_out<<<(BB * HID + 255) / 256, 256>>>(out);
    // NOTE: stream/events intentionally not destroyed here — destroying a
    // stream participating in an active capture invalidates the capture.
    // kernel_launch is called only a handful of times (correctness + capture),
    // so the leaked host handles are bounded and harmless.
}